// round 8
// baseline (speedup 1.0000x reference)
#include <cuda_runtime.h>
#include <cuda_bf16.h>
#include <math.h>
#include <stdint.h>

#define BEFF   1920
#define HID    512
#define FEAT   25
#define ZDIM   256
#define MDIM   512
#define NC3D   58
#define WSTEPS 50
#define GATES  2048

#define TILE_A_BYTES 16384              // 128 rows x 128 B
#define TILE_B_BYTES 32768              // 256 rows x 128 B
#define TILE_B_ELEMS 16384
#define BUF_BYTES (2*TILE_A_BYTES + 2*TILE_B_BYTES)   // 98304
#define DYN_SMEM (2*BUF_BYTES)                         // 196608

// ---------------- device scratch ----------------
__device__ float g_c[BEFF * HID];
__device__ float g_hF[BEFF * HID];
__device__ float g_hy[BEFF * HID];
__device__ float g_base[BEFF * GATES];
__device__ float g_m2[BEFF * MDIM];
__device__ float g_encb[GATES];
__device__ __align__(256) __nv_bfloat16 g_hbf[2][2][BEFF * HID];
__device__ __align__(256) __nv_bfloat16 g_m1bf[2][BEFF * MDIM];
__device__ __align__(256) __nv_bfloat16 g_xbf[2][WSTEPS * BEFF * 64];
__device__ __align__(256) __nv_bfloat16 g_ybf[2][(WSTEPS + 1) * BEFF * 64]; // slot WSTEPS stays 0
__device__ __align__(256) __nv_bfloat16 g_Benc[2][8 * 9 * TILE_B_ELEMS];
__device__ __align__(256) __nv_bfloat16 g_Bdec[2][8 * 9 * TILE_B_ELEMS];
__device__ __align__(256) __nv_bfloat16 g_Bm1[2][2 * 8 * TILE_B_ELEMS];
__device__ __align__(256) __nv_bfloat16 g_Bm2[2][2 * 8 * TILE_B_ELEMS];

// ---------------- helpers ----------------
__device__ __forceinline__ float sigf(float x) { return 1.0f / (1.0f + __expf(-x)); }
__device__ __forceinline__ uint32_t s2u(const void* p) {
    return (uint32_t)__cvta_generic_to_shared(p);
}
__device__ __forceinline__ void cpa4(uint32_t d, const void* s) {
    asm volatile("cp.async.ca.shared.global [%0], [%1], 4;" :: "r"(d), "l"(s));
}
__device__ __forceinline__ void cpa4p(uint32_t d, const void* s, int sz) {
    asm volatile("cp.async.ca.shared.global [%0], [%1], 4, %2;" :: "r"(d), "l"(s), "r"(sz));
}
__device__ __forceinline__ void cpa16(uint32_t d, const void* s) {
    asm volatile("cp.async.cg.shared.global [%0], [%1], 16;" :: "r"(d), "l"(s));
}
__device__ __forceinline__ void cp_commit() { asm volatile("cp.async.commit_group;"); }
__device__ __forceinline__ void cp_wait0()  { asm volatile("cp.async.wait_group 0;"); }
__device__ __forceinline__ void cp_wait1()  { asm volatile("cp.async.wait_group 1;"); }

#define SWZ(o) ((o) ^ (((o) >> 3) & 0x70))

#define LDM_X4(r, a) \
    asm volatile("ldmatrix.sync.aligned.m8n8.x4.shared.b16 {%0,%1,%2,%3}, [%4];" \
        : "=r"((r)[0]), "=r"((r)[1]), "=r"((r)[2]), "=r"((r)[3]) : "r"(a))

#define MMA16816(d, a, b) \
    asm volatile("mma.sync.aligned.m16n8k16.row.col.f32.bf16.bf16.f32 " \
        "{%0,%1,%2,%3}, {%4,%5,%6,%7}, {%8,%9}, {%0,%1,%2,%3};" \
        : "+f"((d)[0]), "+f"((d)[1]), "+f"((d)[2]), "+f"((d)[3]) \
        : "r"((a)[0]), "r"((a)[1]), "r"((a)[2]), "r"((a)[3]), "r"((b)[0]), "r"((b)[1]))

// ---------------- utility kernels ----------------
__global__ void zero_u4(uint4* __restrict__ p, int n) {
    uint4 z = {0, 0, 0, 0};
    for (int i = blockIdx.x * blockDim.x + threadIdx.x; i < n; i += gridDim.x * blockDim.x)
        p[i] = z;
}
__global__ void addvec_kernel(const float* __restrict__ x, const float* __restrict__ y,
                              float* __restrict__ o, int n) {
    int i = blockIdx.x * blockDim.x + threadIdx.x;
    if (i < n) o[i] = x[i] + y[i];
}

// Build pre-swizzled bf16 hi/lo B tiles [nBn][nCh] of 256 rows x 64 k.
__global__ void convW_kernel(const float* __restrict__ W, int ldw, int Kmain, int gateBlocked,
                             const float* __restrict__ Wx, int ldx, int Kx,
                             int nBn, int nCh,
                             __nv_bfloat16* __restrict__ outHi, __nv_bfloat16* __restrict__ outLo) {
    int u = blockIdx.x * blockDim.x + threadIdx.x;
    int total = nBn * nCh * 2048;
    if (u >= total) return;
    int bn = u / (nCh * 2048);
    int rem = u - bn * nCh * 2048;
    int c = rem / 2048;
    int unit = rem & 2047;
    int r = unit >> 3, c16 = unit & 7;
    int srow = gateBlocked ? ((r >> 6) * HID + bn * 64 + (r & 63)) : (bn * 256 + r);
    bool xc = (Wx != nullptr) && (c == nCh - 1);
    unsigned short hb[8], lb[8];
#pragma unroll
    for (int e = 0; e < 8; e++) {
        int k = c16 * 8 + e;
        float v;
        if (xc) v = (k < Kx) ? Wx[(size_t)srow * ldx + k] : 0.0f;
        else {
            int kk = c * 64 + k;
            v = (kk < Kmain) ? W[(size_t)srow * ldw + kk] : 0.0f;
        }
        __nv_bfloat16 h = __float2bfloat16(v);
        hb[e] = __bfloat16_as_ushort(h);
        lb[e] = __bfloat16_as_ushort(__float2bfloat16(v - __bfloat162float(h)));
    }
    uint32_t so = SWZ((uint32_t)(r * 128 + c16 * 16));
    size_t dstu = (size_t)(bn * nCh + c) * 2048 + (so >> 4);
    uint4 vh, vl;
    vh.x = hb[0] | (hb[1] << 16); vh.y = hb[2] | (hb[3] << 16);
    vh.z = hb[4] | (hb[5] << 16); vh.w = hb[6] | (hb[7] << 16);
    vl.x = lb[0] | (lb[1] << 16); vl.y = lb[2] | (lb[3] << 16);
    vl.z = lb[4] | (lb[5] << 16); vl.w = lb[6] | (lb[7] << 16);
    ((uint4*)outHi)[dstu] = vh;
    ((uint4*)outLo)[dstu] = vl;
}

// em (128,750,25) -> x[t][i][64] hi/lo, zero padded
__global__ void convX_kernel(const float* __restrict__ em,
                             __nv_bfloat16* __restrict__ xhi, __nv_bfloat16* __restrict__ xlo) {
    int idx = blockIdx.x * blockDim.x + threadIdx.x;
    if (idx >= WSTEPS * BEFF * 64) return;
    int t = idx / (BEFF * 64);
    int rem = idx - t * BEFF * 64;
    int i = rem >> 6, k = rem & 63;
    float v = (k < FEAT) ? em[(size_t)i * 1250 + t * FEAT + k] : 0.0f;
    __nv_bfloat16 h = __float2bfloat16(v);
    xhi[idx] = h;
    xlo[idx] = __float2bfloat16(v - __bfloat162float(h));
}

// ---------------- SIMT GEMM (small shapes) ----------------
template <int ACT>
__global__ void __launch_bounds__(256, 2)
gemm_kernel(const float* __restrict__ A, int lda,
            const float* __restrict__ W, int ldw,
            const float* __restrict__ b1, const float* __restrict__ b2,
            float* __restrict__ C, int ldc, int N, int K) {
    __shared__ __align__(16) float As[2][16][68];
    __shared__ __align__(16) float Bs[2][16][68];
    const int tid = threadIdx.x;
    const int tx = tid & 15, ty = tid >> 4;
    const int n0 = blockIdx.x * 64, m0 = blockIdx.y * 64;
    const int lk = tid & 15, lr = tid >> 4;
    float acc[4][4] = {};
    const int nch = K >> 4;
    auto issue = [&](int k0, int b) {
#pragma unroll
        for (int i = 0; i < 4; i++) {
            const int row = lr + 16 * i;
            cpa4(s2u(&As[b][lk][row]), &A[(size_t)(n0 + row) * lda + k0 + lk]);
            const int m = m0 + row;
            const int mc = (m < N) ? m : 0;
            cpa4p(s2u(&Bs[b][lk][row]), &W[(size_t)mc * ldw + k0 + lk], (m < N) ? 4 : 0);
        }
        cp_commit();
    };
    issue(0, 0);
    for (int c = 0; c < nch; c++) {
        if (c + 1 < nch) { issue((c + 1) * 16, (c + 1) & 1); cp_wait1(); }
        else             { cp_wait0(); }
        __syncthreads();
        const int p = c & 1;
#pragma unroll
        for (int kk = 0; kk < 16; kk++) {
            float4 a4 = *(const float4*)&As[p][kk][ty * 4];
            float4 b4 = *(const float4*)&Bs[p][kk][tx * 4];
            float av[4] = {a4.x, a4.y, a4.z, a4.w};
            float bv[4] = {b4.x, b4.y, b4.z, b4.w};
#pragma unroll
            for (int r = 0; r < 4; r++)
#pragma unroll
                for (int c2 = 0; c2 < 4; c2++)
                    acc[r][c2] += av[r] * bv[c2];
        }
        __syncthreads();
    }
#pragma unroll
    for (int r = 0; r < 4; r++) {
        const int n = n0 + ty * 4 + r;
#pragma unroll
        for (int c2 = 0; c2 < 4; c2++) {
            const int m = m0 + tx * 4 + c2;
            if (m < N) {
                float v = acc[r][c2];
                if (b1) v += b1[m];
                if (b2) v += b2[m];
                if (ACT == 1) v = tanhf(v);
                C[(size_t)n * ldc + m] = v;
            }
        }
    }
}

// out projection (N=25) + bf16 hi/lo y emit for decoder recurrence
__global__ void __launch_bounds__(256, 2)
outproj_kernel(const float* __restrict__ A, const float* __restrict__ W,
               const float* __restrict__ b, float* __restrict__ pred,
               __nv_bfloat16* __restrict__ yhi, __nv_bfloat16* __restrict__ ylo) {
    __shared__ __align__(16) float As[2][16][68];
    __shared__ __align__(16) float Bs[2][16][68];
    const int tid = threadIdx.x;
    const int tx = tid & 15, ty = tid >> 4;
    const int n0 = blockIdx.x * 64;
    const int lk = tid & 15, lr = tid >> 4;
    float acc[4][4] = {};
    auto issue = [&](int k0, int bb) {
#pragma unroll
        for (int i = 0; i < 4; i++) {
            const int row = lr + 16 * i;
            cpa4(s2u(&As[bb][lk][row]), &A[(size_t)(n0 + row) * MDIM + k0 + lk]);
            const int mc = (row < FEAT) ? row : 0;
            cpa4p(s2u(&Bs[bb][lk][row]), &W[(size_t)mc * MDIM + k0 + lk], (row < FEAT) ? 4 : 0);
        }
        cp_commit();
    };
    issue(0, 0);
    for (int c = 0; c < 32; c++) {
        if (c + 1 < 32) { issue((c + 1) * 16, (c + 1) & 1); cp_wait1(); }
        else            { cp_wait0(); }
        __syncthreads();
        const int p = c & 1;
#pragma unroll
        for (int kk = 0; kk < 16; kk++) {
            float4 a4 = *(const float4*)&As[p][kk][ty * 4];
            float4 b4 = *(const float4*)&Bs[p][kk][tx * 4];
            float av[4] = {a4.x, a4.y, a4.z, a4.w};
            float bv[4] = {b4.x, b4.y, b4.z, b4.w};
#pragma unroll
            for (int r = 0; r < 4; r++)
#pragma unroll
                for (int c2 = 0; c2 < 4; c2++)
                    acc[r][c2] += av[r] * bv[c2];
        }
        __syncthreads();
    }
#pragma unroll
    for (int r = 0; r < 4; r++) {
        const int n = n0 + ty * 4 + r;
#pragma unroll
        for (int c2 = 0; c2 < 4; c2++) {
            const int m = tx * 4 + c2;
            if (m < FEAT) {
                float v = acc[r][c2] + b[m];
                pred[(size_t)n * 1250 + m] = v;
                __nv_bfloat16 h = __float2bfloat16(v);
                yhi[(size_t)n * 64 + m] = h;
                ylo[(size_t)n * 64 + m] = __float2bfloat16(v - __bfloat162float(h));
            }
        }
    }
}

// ---------------- mma.sync GEMM (bf16 3-term split) ----------------
// CTA: 128 batch rows x 256 cols.  16 warps (4 M x 4 N), warp tile 32x64.
// EPI: 0 = LSTM cell, 1 = tanh -> bf16 hi/lo, 2 = tanh -> fp32
template <int NCH, int HASX, int EPI>
__global__ void __launch_bounds__(512)
mma_kernel(const __nv_bfloat16* __restrict__ ahi, const __nv_bfloat16* __restrict__ alo,
           const __nv_bfloat16* __restrict__ xhi, const __nv_bfloat16* __restrict__ xlo,
           const __nv_bfloat16* __restrict__ Bth, const __nv_bfloat16* __restrict__ Btl,
           const float* __restrict__ base, int base_stride,
           const float* __restrict__ bias,
           float* __restrict__ c_io, float* __restrict__ hF,
           __nv_bfloat16* __restrict__ ohi, __nv_bfloat16* __restrict__ olo,
           float* __restrict__ outF) {
    extern __shared__ __align__(1024) char smem[];
    const int tid = threadIdx.x;
    const int wid = tid >> 5;
    const int lane = tid & 31;
    const int n0 = blockIdx.x * 128;
    const int bn = blockIdx.y;
    const int wm = wid & 3;        // M block (32 rows)
    const int wn = wid >> 2;       // N block (64 cols)
    const int ldAmain = (NCH - HASX) * 128;   // bytes per A row

    float acc[2][8][4] = {};

    auto do_copy = [&](int c, int p) {
        char* bb = smem + p * BUF_BYTES;
        uint32_t sAh = s2u(bb), sAl = sAh + TILE_A_BYTES;
        uint32_t sBh = sAh + 2 * TILE_A_BYTES, sBl = sBh + TILE_B_BYTES;
        const char *ap, *alp; int ld;
        if (HASX && c == NCH - 1) { ap = (const char*)xhi; alp = (const char*)xlo; ld = 128; }
        else { ap = (const char*)ahi + c * 128; alp = (const char*)alo + c * 128; ld = ldAmain; }
#pragma unroll
        for (int i = 0; i < 2; i++) {
            int u = tid + i * 512;         // 1024 units of 16B for 128x128B tile
            int r = u >> 3, c16 = u & 7;
            uint32_t so = SWZ((uint32_t)(r * 128 + c16 * 16));
            cpa16(sAh + so, ap + (size_t)(n0 + r) * ld + c16 * 16);
            cpa16(sAl + so, alp + (size_t)(n0 + r) * ld + c16 * 16);
        }
        const char* bh = (const char*)Bth + (size_t)(bn * NCH + c) * TILE_B_BYTES;
        const char* bl = (const char*)Btl + (size_t)(bn * NCH + c) * TILE_B_BYTES;
#pragma unroll
        for (int i = 0; i < 4; i++) {
            int u = tid + i * 512;         // 2048 units
            cpa16(sBh + u * 16, bh + (size_t)u * 16);
            cpa16(sBl + u * 16, bl + (size_t)u * 16);
        }
        cp_commit();
    };

    do_copy(0, 0);
    if (NCH > 1) do_copy(1, 1);
    for (int c = 0; c < NCH; c++) {
        const int p = c & 1;
        if (c + 1 < NCH) cp_wait1(); else cp_wait0();
        __syncthreads();
        uint32_t baseu = s2u(smem + p * BUF_BYTES);
        uint32_t aHb = baseu, aLb = baseu + TILE_A_BYTES;
        uint32_t bHb = baseu + 2 * TILE_A_BYTES, bLb = bHb + TILE_B_BYTES;
#pragma unroll
        for (int ks = 0; ks < 4; ks++) {
            uint32_t ah[2][4], al[2][4];
#pragma unroll
            for (int mi = 0; mi < 2; mi++) {
                int rowA = wm * 32 + mi * 16 + (lane & 15);
                uint32_t off = SWZ((uint32_t)(rowA * 128 + ks * 32 + (lane >> 4) * 16));
                LDM_X4(ah[mi], aHb + off);
                LDM_X4(al[mi], aLb + off);
            }
#pragma unroll
            for (int pr = 0; pr < 4; pr++) {
                int rowB = wn * 64 + pr * 16 + ((lane >> 4) << 3) + (lane & 7);
                uint32_t offB = SWZ((uint32_t)(rowB * 128 + ks * 32 + ((lane >> 3) & 1) * 16));
                uint32_t bh[4], bl[4];
                LDM_X4(bh, bHb + offB);
                LDM_X4(bl, bLb + offB);
#pragma unroll
                for (int mi = 0; mi < 2; mi++) {
#pragma unroll
                    for (int t2 = 0; t2 < 2; t2++) {
                        float* d = acc[mi][pr * 2 + t2];
                        MMA16816(d, ah[mi], bh + t2 * 2);
                        MMA16816(d, ah[mi], bl + t2 * 2);
                        MMA16816(d, al[mi], bh + t2 * 2);
                    }
                }
            }
        }
        __syncthreads();
        if (c + 2 < NCH) do_copy(c + 2, p);
    }

    // stage accumulators to smem: sAcc[128][256] fp32
    float* sAcc = (float*)smem;
#pragma unroll
    for (int mi = 0; mi < 2; mi++) {
#pragma unroll
        for (int ni = 0; ni < 8; ni++) {
            int row = wm * 32 + mi * 16 + (lane >> 2);
            int col = wn * 64 + ni * 8 + 2 * (lane & 3);
            *(float2*)&sAcc[row * 256 + col] = make_float2(acc[mi][ni][0], acc[mi][ni][1]);
            *(float2*)&sAcc[(row + 8) * 256 + col] = make_float2(acc[mi][ni][2], acc[mi][ni][3]);
        }
    }
    __syncthreads();

    const int row = tid >> 2;
    const int n = n0 + row;
    if (EPI == 0) {
        const int j0 = bn * 64;
        const int jq = tid & 3;
        const float* bp = base + (size_t)n * base_stride;
#pragma unroll
        for (int q = 0; q < 16; q++) {
            int jl = jq * 16 + q;
            float iv = sAcc[row * 256 + jl]        + bp[j0 + jl];
            float fv = sAcc[row * 256 + 64 + jl]   + bp[512 + j0 + jl];
            float gv = sAcc[row * 256 + 128 + jl]  + bp[1024 + j0 + jl];
            float ov = sAcc[row * 256 + 192 + jl]  + bp[1536 + j0 + jl];
            float cold = c_io[(size_t)n * HID + j0 + jl];
            float cn = sigf(fv) * cold + sigf(iv) * tanhf(gv);
            float hn = sigf(ov) * tanhf(cn);
            c_io[(size_t)n * HID + j0 + jl] = cn;
            hF[(size_t)n * HID + j0 + jl] = hn;
            __nv_bfloat16 h = __float2bfloat16(hn);
            ohi[(size_t)n * HID + j0 + jl] = h;
            olo[(size_t)n * HID + j0 + jl] = __float2bfloat16(hn - __bfloat162float(h));
        }
    } else {
        const int cg = tid & 3;
#pragma unroll
        for (int q = 0; q < 64; q++) {
            int col = cg * 64 + q;
            int gcol = bn * 256 + col;
            float v = tanhf(sAcc[row * 256 + col] + bias[gcol]);
            if (EPI == 2) {
                outF[(size_t)n * MDIM + gcol] = v;
            } else {
                __nv_bfloat16 h = __float2bfloat16(v);
                ohi[(size_t)n * MDIM + gcol] = h;
                olo[(size_t)n * MDIM + gcol] = __float2bfloat16(v - __bfloat162float(h));
            }
        }
    }
}

// ---------------- fused 3DMM head ----------------
__global__ void __launch_bounds__(256)
head3dmm_kernel(const float* __restrict__ pred,
                const float* __restrict__ C1, const float* __restrict__ b1,
                const float* __restrict__ C2, const float* __restrict__ b2,
                float* __restrict__ coeff) {
    __shared__ __align__(16) float sP[64][FEAT + 1];
    __shared__ __align__(16) float sC1c[64][FEAT + 1];
    __shared__ __align__(16) float sHid[64][64];
    const int tid = threadIdx.x;
    const int r0 = blockIdx.x * 64;
    for (int i = tid; i < 64 * FEAT; i += 256)
        sP[i / FEAT][i % FEAT] = pred[(size_t)(r0 + i / FEAT) * FEAT + i % FEAT];
    const int row = tid >> 2;
    const int l4 = tid & 3;
    float acc[15];
#pragma unroll
    for (int q = 0; q < 15; q++) acc[q] = 0.0f;
    for (int jc = 0; jc < HID; jc += 64) {
        __syncthreads();
        for (int i = tid; i < 64 * FEAT; i += 256)
            sC1c[i / FEAT][i % FEAT] = C1[(size_t)(jc + i / FEAT) * FEAT + i % FEAT];
        __syncthreads();
#pragma unroll
        for (int jj = 0; jj < 16; jj++) {
            const int jl = l4 * 16 + jj;
            float v = b1[jc + jl];
#pragma unroll
            for (int k = 0; k < FEAT; k++)
                v += sP[row][k] * sC1c[jl][k];
            sHid[row][jl] = tanhf(v);
        }
        __syncthreads();
        for (int q = 0; q < 15; q++) {
            const int m = l4 + q * 4;
            if (m < NC3D) {
                float s = 0.0f;
                const float* c2r = C2 + (size_t)m * HID + jc;
#pragma unroll
                for (int jj = 0; jj < 64; jj++)
                    s += sHid[row][jj] * c2r[jj];
                acc[q] += s;
            }
        }
    }
#pragma unroll
    for (int q = 0; q < 15; q++) {
        const int m = l4 + q * 4;
        if (m < NC3D)
            coeff[(size_t)(r0 + row) * NC3D + m] = acc[q] + b2[m];
    }
}

// ---------------- host orchestration ----------------
extern "C" void kernel_launch(void* const* d_in, const int* in_sizes, int n_in,
                              void* d_out, int out_size) {
    const float* em   = (const float*)d_in[0];
    const float* eWih = (const float*)d_in[2];
    const float* eWhh = (const float*)d_in[3];
    const float* ebih = (const float*)d_in[4];
    const float* ebhh = (const float*)d_in[5];
    const float* muW  = (const float*)d_in[6];
    const float* mub  = (const float*)d_in[7];
    const float* lvW  = (const float*)d_in[8];
    const float* lvb  = (const float*)d_in[9];
    const float* zW   = (const float*)d_in[10];
    const float* zb   = (const float*)d_in[11];
    const float* dWih = (const float*)d_in[12];
    const float* dWhh = (const float*)d_in[13];
    const float* dbih = (const float*)d_in[14];
    const float* dbhh = (const float*)d_in[15];
    const float* m1W  = (const float*)d_in[16];
    const float* m1b  = (const float*)d_in[17];
    const float* m2W  = (const float*)d_in[18];
    const float* m2b  = (const float*)d_in[19];
    const float* oW   = (const float*)d_in[20];
    const float* ob   = (const float*)d_in[21];
    const float* c1W  = (const float*)d_in[22];
    const float* c1b  = (const float*)d_in[23];
    const float* c2W  = (const float*)d_in[24];
    const float* c2b  = (const float*)d_in[25];

    float* out   = (float*)d_out;
    float* pred  = out;
    float* coeff = out + 2400000;
    float* mu    = out + 2400000 + 5568000;
    float* lv    = mu + 491520;

    float *cbuf, *hF, *hy, *base, *m2, *encb;
    __nv_bfloat16 *hbf, *m1bf, *xbf, *ybf, *Benc, *Bdec, *Bm1, *Bm2;
    cudaGetSymbolAddress((void**)&cbuf, g_c);
    cudaGetSymbolAddress((void**)&hF,   g_hF);
    cudaGetSymbolAddress((void**)&hy,   g_hy);
    cudaGetSymbolAddress((void**)&base, g_base);
    cudaGetSymbolAddress((void**)&m2,   g_m2);
    cudaGetSymbolAddress((void**)&encb, g_encb);
    cudaGetSymbolAddress((void**)&hbf,  g_hbf);
    cudaGetSymbolAddress((void**)&m1bf, g_m1bf);
    cudaGetSymbolAddress((void**)&xbf,  g_xbf);
    cudaGetSymbolAddress((void**)&ybf,  g_ybf);
    cudaGetSymbolAddress((void**)&Benc, g_Benc);
    cudaGetSymbolAddress((void**)&Bdec, g_Bdec);
    cudaGetSymbolAddress((void**)&Bm1,  g_Bm1);
    cudaGetSymbolAddress((void**)&Bm2,  g_Bm2);
    const size_t HSZ = (size_t)BEFF * HID;
    const size_t XSL = (size_t)BEFF * 64;
    __nv_bfloat16* hbfp[2][2] = {{hbf, hbf + HSZ}, {hbf + 2 * HSZ, hbf + 3 * HSZ}};
    __nv_bfloat16* BencL = Benc + 8 * 9 * TILE_B_ELEMS;
    __nv_bfloat16* BdecL = Bdec + 8 * 9 * TILE_B_ELEMS;
    __nv_bfloat16* Bm1L = Bm1 + 2 * 8 * TILE_B_ELEMS;
    __nv_bfloat16* Bm2L = Bm2 + 2 * 8 * TILE_B_ELEMS;
    __nv_bfloat16* xlo = xbf + (size_t)WSTEPS * XSL;
    __nv_bfloat16* ylo = ybf + (size_t)(WSTEPS + 1) * XSL;

    cudaFuncSetAttribute(mma_kernel<9,1,0>, cudaFuncAttributeMaxDynamicSharedMemorySize, DYN_SMEM);
    cudaFuncSetAttribute(mma_kernel<8,0,1>, cudaFuncAttributeMaxDynamicSharedMemorySize, DYN_SMEM);
    cudaFuncSetAttribute(mma_kernel<8,0,2>, cudaFuncAttributeMaxDynamicSharedMemorySize, DYN_SMEM);

    const dim3 blk(256);
    // weight/input conversion (deterministic each call)
    convW_kernel<<<(8*9*2048+255)/256, blk>>>(eWhh, 512, 512, 1, eWih, 25, 25, 8, 9, Benc, BencL);
    convW_kernel<<<(8*9*2048+255)/256, blk>>>(dWhh, 512, 512, 1, dWih + 512, 537, 25, 8, 9, Bdec, BdecL);
    convW_kernel<<<(2*8*2048+255)/256, blk>>>(m1W, 512, 512, 0, nullptr, 0, 0, 2, 8, Bm1, Bm1L);
    convW_kernel<<<(2*8*2048+255)/256, blk>>>(m2W, 512, 512, 0, nullptr, 0, 0, 2, 8, Bm2, Bm2L);
    convX_kernel<<<(WSTEPS*BEFF*64+255)/256, blk>>>(em, xbf, xlo);
    addvec_kernel<<<8, blk>>>(ebih, ebhh, encb, GATES);
    // zero c + h bf16 buf0 (hi+lo)
    zero_u4<<<256, blk>>>((uint4*)cbuf, (int)(HSZ / 4));
    zero_u4<<<256, blk>>>((uint4*)hbfp[0][0], (int)(HSZ / 8));
    zero_u4<<<256, blk>>>((uint4*)hbfp[0][1], (int)(HSZ / 8));

    // ---- encoder ----
    for (int t = 0; t < WSTEPS; t++) {
        int s = t & 1, d = s ^ 1;
        mma_kernel<9,1,0><<<dim3(15, 8), 512, DYN_SMEM>>>(
            hbfp[s][0], hbfp[s][1], xbf + (size_t)t * XSL, xlo + (size_t)t * XSL,
            Benc, BencL, encb, 0, nullptr, cbuf, hF, hbfp[d][0], hbfp[d][1], nullptr);
    }

    // ---- latent head ----
    gemm_kernel<0><<<dim3(30, 4), blk>>>(hF, HID, muW, HID, mub, nullptr, mu, ZDIM, ZDIM, HID);
    gemm_kernel<0><<<dim3(30, 4), blk>>>(hF, HID, lvW, HID, lvb, nullptr, lv, ZDIM, ZDIM, HID);
    gemm_kernel<0><<<dim3(30, 8), blk>>>(mu, ZDIM, zW, ZDIM, zb, nullptr, hy, HID, HID, ZDIM);
    gemm_kernel<0><<<dim3(30, 32), blk>>>(hy, HID, dWih, HID + FEAT, dbih, dbhh,
                                          base, GATES, GATES, HID);

    // reset state for decoder
    zero_u4<<<256, blk>>>((uint4*)cbuf, (int)(HSZ / 4));
    zero_u4<<<256, blk>>>((uint4*)hbfp[0][0], (int)(HSZ / 8));
    zero_u4<<<256, blk>>>((uint4*)hbfp[0][1], (int)(HSZ / 8));

    // ---- decoder ----
    for (int t = 0; t < WSTEPS; t++) {
        int s = t & 1, d = s ^ 1;
        const __nv_bfloat16* yh = (t == 0) ? (ybf + (size_t)WSTEPS * XSL) : (ybf + (size_t)(t - 1) * XSL);
        const __nv_bfloat16* yl = (t == 0) ? (ylo + (size_t)WSTEPS * XSL) : (ylo + (size_t)(t - 1) * XSL);
        mma_kernel<9,1,0><<<dim3(15, 8), 512, DYN_SMEM>>>(
            hbfp[s][0], hbfp[s][1], yh, yl,
            Bdec, BdecL, base, GATES, nullptr, cbuf, hF, hbfp[d][0], hbfp[d][1], nullptr);
        mma_kernel<8,0,1><<<dim3(15, 2), 512, DYN_SMEM>>>(
            hbfp[d][0], hbfp[d][1], nullptr, nullptr,
            Bm1, Bm1L, nullptr, 0, m1b, nullptr, nullptr, m1bf, m1bf + HSZ, nullptr);
        mma_kernel<8,0,2><<<dim3(15, 2), 512, DYN_SMEM>>>(
            m1bf, m1bf + HSZ, nullptr, nullptr,
            Bm2, Bm2L, nullptr, 0, m2b, nullptr, nullptr, nullptr, nullptr, m2);
        outproj_kernel<<<30, blk>>>(m2, oW, ob, pred + t * FEAT,
                                    ybf + (size_t)t * XSL, ylo + (size_t)t * XSL);
    }

    // ---- 3DMM head ----
    head3dmm_kernel<<<1500, blk>>>(pred, c1W, c1b, c2W, c2b, coeff);
}

// round 10
// speedup vs baseline: 1.5509x; 1.5509x over previous
#include <cuda_runtime.h>
#include <cuda_bf16.h>
#include <math.h>
#include <stdint.h>

#define BEFF   1920
#define HID    512
#define FEAT   25
#define ZDIM   256
#define MDIM   512
#define NC3D   58
#define WSTEPS 50
#define GATES  2048

#define TILE_A_BYTES 16384              // 128 rows x 128 B
#define TILE_B_BYTES 32768              // 256 rows x 128 B
#define TILE_B_ELEMS 16384
#define BUF_BYTES (2*TILE_A_BYTES + 2*TILE_B_BYTES)   // 98304
#define DYN_SMEM (2*BUF_BYTES)                         // 196608

// ---------------- device scratch ----------------
__device__ float g_c[BEFF * HID];
__device__ float g_hF[BEFF * HID];
__device__ float g_hy[BEFF * HID];
__device__ float g_base[BEFF * GATES];
__device__ float g_m2[BEFF * MDIM];
__device__ float g_encb[GATES];
__device__ __align__(256) __nv_bfloat16 g_hbf[2][2][BEFF * HID];
__device__ __align__(256) __nv_bfloat16 g_m1bf[2][BEFF * MDIM];
__device__ __align__(256) __nv_bfloat16 g_xbf[2][WSTEPS * BEFF * 64];
__device__ __align__(256) __nv_bfloat16 g_ybf[2][(WSTEPS + 1) * BEFF * 64]; // slot WSTEPS stays 0
__device__ __align__(256) __nv_bfloat16 g_Benc[2][8 * 9 * TILE_B_ELEMS];
__device__ __align__(256) __nv_bfloat16 g_Bdec[2][8 * 9 * TILE_B_ELEMS];
__device__ __align__(256) __nv_bfloat16 g_Bm1[2][2 * 8 * TILE_B_ELEMS];
__device__ __align__(256) __nv_bfloat16 g_Bm2[2][2 * 8 * TILE_B_ELEMS];

// ---------------- helpers ----------------
__device__ __forceinline__ float sigf(float x) { return 1.0f / (1.0f + __expf(-x)); }
__device__ __forceinline__ uint32_t s2u(const void* p) {
    return (uint32_t)__cvta_generic_to_shared(p);
}
__device__ __forceinline__ void cpa4(uint32_t d, const void* s) {
    asm volatile("cp.async.ca.shared.global [%0], [%1], 4;" :: "r"(d), "l"(s));
}
__device__ __forceinline__ void cpa4p(uint32_t d, const void* s, int sz) {
    asm volatile("cp.async.ca.shared.global [%0], [%1], 4, %2;" :: "r"(d), "l"(s), "r"(sz));
}
__device__ __forceinline__ void cpa16(uint32_t d, const void* s) {
    asm volatile("cp.async.cg.shared.global [%0], [%1], 16;" :: "r"(d), "l"(s));
}
__device__ __forceinline__ void cp_commit() { asm volatile("cp.async.commit_group;"); }
__device__ __forceinline__ void cp_wait0()  { asm volatile("cp.async.wait_group 0;"); }
__device__ __forceinline__ void cp_wait1()  { asm volatile("cp.async.wait_group 1;"); }

#define SWZ(o) ((o) ^ (((o) >> 3) & 0x70))

#define LDM_X4(r, a) \
    asm volatile("ldmatrix.sync.aligned.m8n8.x4.shared.b16 {%0,%1,%2,%3}, [%4];" \
        : "=r"((r)[0]), "=r"((r)[1]), "=r"((r)[2]), "=r"((r)[3]) : "r"(a))

#define MMA16816(d, a, b) \
    asm volatile("mma.sync.aligned.m16n8k16.row.col.f32.bf16.bf16.f32 " \
        "{%0,%1,%2,%3}, {%4,%5,%6,%7}, {%8,%9}, {%0,%1,%2,%3};" \
        : "+f"((d)[0]), "+f"((d)[1]), "+f"((d)[2]), "+f"((d)[3]) \
        : "r"((a)[0]), "r"((a)[1]), "r"((a)[2]), "r"((a)[3]), "r"((b)[0]), "r"((b)[1]))

// ---------------- utility kernels ----------------
__global__ void zero_u4(uint4* __restrict__ p, int n) {
    uint4 z = {0, 0, 0, 0};
    for (int i = blockIdx.x * blockDim.x + threadIdx.x; i < n; i += gridDim.x * blockDim.x)
        p[i] = z;
}
__global__ void addvec_kernel(const float* __restrict__ x, const float* __restrict__ y,
                              float* __restrict__ o, int n) {
    int i = blockIdx.x * blockDim.x + threadIdx.x;
    if (i < n) o[i] = x[i] + y[i];
}

// Build pre-swizzled bf16 hi/lo B tiles [nBn][nCh] of 256 rows x 64 k.
__global__ void convW_kernel(const float* __restrict__ W, int ldw, int Kmain, int gateBlocked,
                             const float* __restrict__ Wx, int ldx, int Kx,
                             int nBn, int nCh,
                             __nv_bfloat16* __restrict__ outHi, __nv_bfloat16* __restrict__ outLo) {
    int u = blockIdx.x * blockDim.x + threadIdx.x;
    int total = nBn * nCh * 2048;
    if (u >= total) return;
    int bn = u / (nCh * 2048);
    int rem = u - bn * nCh * 2048;
    int c = rem / 2048;
    int unit = rem & 2047;
    int r = unit >> 3, c16 = unit & 7;
    int srow = gateBlocked ? ((r >> 6) * HID + bn * 64 + (r & 63)) : (bn * 256 + r);
    bool xc = (Wx != nullptr) && (c == nCh - 1);
    unsigned short hb[8], lb[8];
#pragma unroll
    for (int e = 0; e < 8; e++) {
        int k = c16 * 8 + e;
        float v;
        if (xc) v = (k < Kx) ? Wx[(size_t)srow * ldx + k] : 0.0f;
        else {
            int kk = c * 64 + k;
            v = (kk < Kmain) ? W[(size_t)srow * ldw + kk] : 0.0f;
        }
        __nv_bfloat16 h = __float2bfloat16(v);
        hb[e] = __bfloat16_as_ushort(h);
        lb[e] = __bfloat16_as_ushort(__float2bfloat16(v - __bfloat162float(h)));
    }
    uint32_t so = SWZ((uint32_t)(r * 128 + c16 * 16));
    size_t dstu = (size_t)(bn * nCh + c) * 2048 + (so >> 4);
    uint4 vh, vl;
    vh.x = hb[0] | (hb[1] << 16); vh.y = hb[2] | (hb[3] << 16);
    vh.z = hb[4] | (hb[5] << 16); vh.w = hb[6] | (hb[7] << 16);
    vl.x = lb[0] | (lb[1] << 16); vl.y = lb[2] | (lb[3] << 16);
    vl.z = lb[4] | (lb[5] << 16); vl.w = lb[6] | (lb[7] << 16);
    ((uint4*)outHi)[dstu] = vh;
    ((uint4*)outLo)[dstu] = vl;
}

// em (128,750,25) -> x[t][i][64] hi/lo, zero padded
__global__ void convX_kernel(const float* __restrict__ em,
                             __nv_bfloat16* __restrict__ xhi, __nv_bfloat16* __restrict__ xlo) {
    int idx = blockIdx.x * blockDim.x + threadIdx.x;
    if (idx >= WSTEPS * BEFF * 64) return;
    int t = idx / (BEFF * 64);
    int rem = idx - t * BEFF * 64;
    int i = rem >> 6, k = rem & 63;
    float v = (k < FEAT) ? em[(size_t)i * 1250 + t * FEAT + k] : 0.0f;
    __nv_bfloat16 h = __float2bfloat16(v);
    xhi[idx] = h;
    xlo[idx] = __float2bfloat16(v - __bfloat162float(h));
}

// ---------------- SIMT GEMM (small shapes) ----------------
template <int ACT>
__global__ void __launch_bounds__(256, 2)
gemm_kernel(const float* __restrict__ A, int lda,
            const float* __restrict__ W, int ldw,
            const float* __restrict__ b1, const float* __restrict__ b2,
            float* __restrict__ C, int ldc, int N, int K) {
    __shared__ __align__(16) float As[2][16][68];
    __shared__ __align__(16) float Bs[2][16][68];
    const int tid = threadIdx.x;
    const int tx = tid & 15, ty = tid >> 4;
    const int n0 = blockIdx.x * 64, m0 = blockIdx.y * 64;
    const int lk = tid & 15, lr = tid >> 4;
    float acc[4][4] = {};
    const int nch = K >> 4;
    auto issue = [&](int k0, int b) {
#pragma unroll
        for (int i = 0; i < 4; i++) {
            const int row = lr + 16 * i;
            cpa4(s2u(&As[b][lk][row]), &A[(size_t)(n0 + row) * lda + k0 + lk]);
            const int m = m0 + row;
            const int mc = (m < N) ? m : 0;
            cpa4p(s2u(&Bs[b][lk][row]), &W[(size_t)mc * ldw + k0 + lk], (m < N) ? 4 : 0);
        }
        cp_commit();
    };
    issue(0, 0);
    for (int c = 0; c < nch; c++) {
        if (c + 1 < nch) { issue((c + 1) * 16, (c + 1) & 1); cp_wait1(); }
        else             { cp_wait0(); }
        __syncthreads();
        const int p = c & 1;
#pragma unroll
        for (int kk = 0; kk < 16; kk++) {
            float4 a4 = *(const float4*)&As[p][kk][ty * 4];
            float4 b4 = *(const float4*)&Bs[p][kk][tx * 4];
            float av[4] = {a4.x, a4.y, a4.z, a4.w};
            float bv[4] = {b4.x, b4.y, b4.z, b4.w};
#pragma unroll
            for (int r = 0; r < 4; r++)
#pragma unroll
                for (int c2 = 0; c2 < 4; c2++)
                    acc[r][c2] += av[r] * bv[c2];
        }
        __syncthreads();
    }
#pragma unroll
    for (int r = 0; r < 4; r++) {
        const int n = n0 + ty * 4 + r;
#pragma unroll
        for (int c2 = 0; c2 < 4; c2++) {
            const int m = m0 + tx * 4 + c2;
            if (m < N) {
                float v = acc[r][c2];
                if (b1) v += b1[m];
                if (b2) v += b2[m];
                if (ACT == 1) v = tanhf(v);
                C[(size_t)n * ldc + m] = v;
            }
        }
    }
}

// out projection (N=25) + bf16 hi/lo y emit for decoder recurrence
__global__ void __launch_bounds__(256, 2)
outproj_kernel(const float* __restrict__ A, const float* __restrict__ W,
               const float* __restrict__ b, float* __restrict__ pred,
               __nv_bfloat16* __restrict__ yhi, __nv_bfloat16* __restrict__ ylo) {
    __shared__ __align__(16) float As[2][16][68];
    __shared__ __align__(16) float Bs[2][16][68];
    const int tid = threadIdx.x;
    const int tx = tid & 15, ty = tid >> 4;
    const int n0 = blockIdx.x * 64;
    const int lk = tid & 15, lr = tid >> 4;
    float acc[4][4] = {};
    auto issue = [&](int k0, int bb) {
#pragma unroll
        for (int i = 0; i < 4; i++) {
            const int row = lr + 16 * i;
            cpa4(s2u(&As[bb][lk][row]), &A[(size_t)(n0 + row) * MDIM + k0 + lk]);
            const int mc = (row < FEAT) ? row : 0;
            cpa4p(s2u(&Bs[bb][lk][row]), &W[(size_t)mc * MDIM + k0 + lk], (row < FEAT) ? 4 : 0);
        }
        cp_commit();
    };
    issue(0, 0);
    for (int c = 0; c < 32; c++) {
        if (c + 1 < 32) { issue((c + 1) * 16, (c + 1) & 1); cp_wait1(); }
        else            { cp_wait0(); }
        __syncthreads();
        const int p = c & 1;
#pragma unroll
        for (int kk = 0; kk < 16; kk++) {
            float4 a4 = *(const float4*)&As[p][kk][ty * 4];
            float4 b4 = *(const float4*)&Bs[p][kk][tx * 4];
            float av[4] = {a4.x, a4.y, a4.z, a4.w};
            float bv[4] = {b4.x, b4.y, b4.z, b4.w};
#pragma unroll
            for (int r = 0; r < 4; r++)
#pragma unroll
                for (int c2 = 0; c2 < 4; c2++)
                    acc[r][c2] += av[r] * bv[c2];
        }
        __syncthreads();
    }
#pragma unroll
    for (int r = 0; r < 4; r++) {
        const int n = n0 + ty * 4 + r;
#pragma unroll
        for (int c2 = 0; c2 < 4; c2++) {
            const int m = tx * 4 + c2;
            if (m < FEAT) {
                float v = acc[r][c2] + b[m];
                pred[(size_t)n * 1250 + m] = v;
                __nv_bfloat16 h = __float2bfloat16(v);
                yhi[(size_t)n * 64 + m] = h;
                ylo[(size_t)n * 64 + m] = __float2bfloat16(v - __bfloat162float(h));
            }
        }
    }
}

// ---------------- mma.sync GEMM (bf16 3-term split) ----------------
// CTA: 128 batch rows x 256 cols. 256 threads = 8 warps (2 M x 4 N), warp tile 64x64.
// 128 acc regs/thread; 256 thr/CTA -> 255-reg budget, no spills.
// EPI: 0 = LSTM cell, 1 = tanh -> bf16 hi/lo, 2 = tanh -> fp32
template <int NCH, int HASX, int EPI>
__global__ void __launch_bounds__(256)
mma_kernel(const __nv_bfloat16* __restrict__ ahi, const __nv_bfloat16* __restrict__ alo,
           const __nv_bfloat16* __restrict__ xhi, const __nv_bfloat16* __restrict__ xlo,
           const __nv_bfloat16* __restrict__ Bth, const __nv_bfloat16* __restrict__ Btl,
           const float* __restrict__ base, int base_stride,
           const float* __restrict__ bias,
           float* __restrict__ c_io, float* __restrict__ hF,
           __nv_bfloat16* __restrict__ ohi, __nv_bfloat16* __restrict__ olo,
           float* __restrict__ outF) {
    extern __shared__ __align__(1024) char smem[];
    const int tid = threadIdx.x;
    const int wid = tid >> 5;
    const int lane = tid & 31;
    const int n0 = blockIdx.x * 128;
    const int bn = blockIdx.y;
    const int wm = wid & 1;        // M block (64 rows)
    const int wn = wid >> 1;       // N block (64 cols)
    const int ldAmain = (NCH - HASX) * 128;   // bytes per A row

    float acc[4][8][4] = {};       // [mi 16-row][n8 group][frag]

    auto do_copy = [&](int c, int p) {
        char* bb = smem + p * BUF_BYTES;
        uint32_t sAh = s2u(bb), sAl = sAh + TILE_A_BYTES;
        uint32_t sBh = sAh + 2 * TILE_A_BYTES, sBl = sBh + TILE_B_BYTES;
        const char *ap, *alp; int ld;
        if (HASX && c == NCH - 1) { ap = (const char*)xhi; alp = (const char*)xlo; ld = 128; }
        else { ap = (const char*)ahi + c * 128; alp = (const char*)alo + c * 128; ld = ldAmain; }
#pragma unroll
        for (int i = 0; i < 4; i++) {
            int u = tid + i * 256;         // 1024 units of 16B for 128x128B tile
            int r = u >> 3, c16 = u & 7;
            uint32_t so = SWZ((uint32_t)(r * 128 + c16 * 16));
            cpa16(sAh + so, ap + (size_t)(n0 + r) * ld + c16 * 16);
            cpa16(sAl + so, alp + (size_t)(n0 + r) * ld + c16 * 16);
        }
        const char* bh = (const char*)Bth + (size_t)(bn * NCH + c) * TILE_B_BYTES;
        const char* bl = (const char*)Btl + (size_t)(bn * NCH + c) * TILE_B_BYTES;
#pragma unroll
        for (int i = 0; i < 8; i++) {
            int u = tid + i * 256;         // 2048 units
            cpa16(sBh + u * 16, bh + (size_t)u * 16);
            cpa16(sBl + u * 16, bl + (size_t)u * 16);
        }
        cp_commit();
    };

    do_copy(0, 0);
    if (NCH > 1) do_copy(1, 1);
    for (int c = 0; c < NCH; c++) {
        const int p = c & 1;
        if (c + 1 < NCH) cp_wait1(); else cp_wait0();
        __syncthreads();
        uint32_t baseu = s2u(smem + p * BUF_BYTES);
        uint32_t aHb = baseu, aLb = baseu + TILE_A_BYTES;
        uint32_t bHb = baseu + 2 * TILE_A_BYTES, bLb = bHb + TILE_B_BYTES;
#pragma unroll
        for (int ks = 0; ks < 4; ks++) {
            uint32_t ah[4][4], al[4][4];
#pragma unroll
            for (int mi = 0; mi < 4; mi++) {
                int rowA = wm * 64 + mi * 16 + (lane & 15);
                uint32_t off = SWZ((uint32_t)(rowA * 128 + ks * 32 + (lane >> 4) * 16));
                LDM_X4(ah[mi], aHb + off);
                LDM_X4(al[mi], aLb + off);
            }
#pragma unroll
            for (int pr = 0; pr < 4; pr++) {
                int rowB = wn * 64 + pr * 16 + ((lane >> 4) << 3) + (lane & 7);
                uint32_t offB = SWZ((uint32_t)(rowB * 128 + ks * 32 + ((lane >> 3) & 1) * 16));
                uint32_t bh[4], bl[4];
                LDM_X4(bh, bHb + offB);
                LDM_X4(bl, bLb + offB);
#pragma unroll
                for (int mi = 0; mi < 4; mi++) {
#pragma unroll
                    for (int t2 = 0; t2 < 2; t2++) {
                        float* d = acc[mi][pr * 2 + t2];
                        MMA16816(d, ah[mi], bh + t2 * 2);
                        MMA16816(d, ah[mi], bl + t2 * 2);
                        MMA16816(d, al[mi], bh + t2 * 2);
                    }
                }
            }
        }
        __syncthreads();
        if (c + 2 < NCH) do_copy(c + 2, p);
    }

    // stage accumulators to smem: sAcc[128][256] fp32 (128 KB)
    float* sAcc = (float*)smem;
#pragma unroll
    for (int mi = 0; mi < 4; mi++) {
#pragma unroll
        for (int ni = 0; ni < 8; ni++) {
            int row = wm * 64 + mi * 16 + (lane >> 2);
            int col = wn * 64 + ni * 8 + 2 * (lane & 3);
            *(float2*)&sAcc[row * 256 + col] = make_float2(acc[mi][ni][0], acc[mi][ni][1]);
            *(float2*)&sAcc[(row + 8) * 256 + col] = make_float2(acc[mi][ni][2], acc[mi][ni][3]);
        }
    }
    __syncthreads();

    const int rgrp = tid >> 6;       // 0..3
    const int col = tid & 63;        // 0..63 (consecutive per warp -> coalesced)
    if (EPI == 0) {
        const int j0 = bn * 64;
        const int j = j0 + col;
#pragma unroll 4
        for (int rr = 0; rr < 32; rr++) {
            int row = rr * 4 + rgrp;
            int n = n0 + row;
            const float* bp = base + (size_t)n * base_stride;
            float iv = sAcc[row * 256 + col]       + bp[j];
            float fv = sAcc[row * 256 + 64 + col]  + bp[512 + j];
            float gv = sAcc[row * 256 + 128 + col] + bp[1024 + j];
            float ov = sAcc[row * 256 + 192 + col] + bp[1536 + j];
            float cold = c_io[(size_t)n * HID + j];
            float cn = sigf(fv) * cold + sigf(iv) * tanhf(gv);
            float hn = sigf(ov) * tanhf(cn);
            c_io[(size_t)n * HID + j] = cn;
            hF[(size_t)n * HID + j] = hn;
            __nv_bfloat16 h = __float2bfloat16(hn);
            ohi[(size_t)n * HID + j] = h;
            olo[(size_t)n * HID + j] = __float2bfloat16(hn - __bfloat162float(h));
        }
    } else {
#pragma unroll 2
        for (int rr = 0; rr < 32; rr++) {
            int row = rr * 4 + rgrp;
            int n = n0 + row;
#pragma unroll
            for (int cg = 0; cg < 4; cg++) {
                int colx = cg * 64 + col;
                int gcol = bn * 256 + colx;
                float v = tanhf(sAcc[row * 256 + colx] + bias[gcol]);
                if (EPI == 2) {
                    outF[(size_t)n * MDIM + gcol] = v;
                } else {
                    __nv_bfloat16 h = __float2bfloat16(v);
                    ohi[(size_t)n * MDIM + gcol] = h;
                    olo[(size_t)n * MDIM + gcol] = __float2bfloat16(v - __bfloat162float(h));
                }
            }
        }
    }
}

// ---------------- fused 3DMM head ----------------
__global__ void __launch_bounds__(256)
head3dmm_kernel(const float* __restrict__ pred,
                const float* __restrict__ C1, const float* __restrict__ b1,
                const float* __restrict__ C2, const float* __restrict__ b2,
                float* __restrict__ coeff) {
    __shared__ __align__(16) float sP[64][FEAT + 1];
    __shared__ __align__(16) float sC1c[64][FEAT + 1];
    __shared__ __align__(16) float sHid[64][64];
    const int tid = threadIdx.x;
    const int r0 = blockIdx.x * 64;
    for (int i = tid; i < 64 * FEAT; i += 256)
        sP[i / FEAT][i % FEAT] = pred[(size_t)(r0 + i / FEAT) * FEAT + i % FEAT];
    const int row = tid >> 2;
    const int l4 = tid & 3;
    float acc[15];
#pragma unroll
    for (int q = 0; q < 15; q++) acc[q] = 0.0f;
    for (int jc = 0; jc < HID; jc += 64) {
        __syncthreads();
        for (int i = tid; i < 64 * FEAT; i += 256)
            sC1c[i / FEAT][i % FEAT] = C1[(size_t)(jc + i / FEAT) * FEAT + i % FEAT];
        __syncthreads();
#pragma unroll
        for (int jj = 0; jj < 16; jj++) {
            const int jl = l4 * 16 + jj;
            float v = b1[jc + jl];
#pragma unroll
            for (int k = 0; k < FEAT; k++)
                v += sP[row][k] * sC1c[jl][k];
            sHid[row][jl] = tanhf(v);
        }
        __syncthreads();
        for (int q = 0; q < 15; q++) {
            const int m = l4 + q * 4;
            if (m < NC3D) {
                float s = 0.0f;
                const float* c2r = C2 + (size_t)m * HID + jc;
#pragma unroll
                for (int jj = 0; jj < 64; jj++)
                    s += sHid[row][jj] * c2r[jj];
                acc[q] += s;
            }
        }
    }
#pragma unroll
    for (int q = 0; q < 15; q++) {
        const int m = l4 + q * 4;
        if (m < NC3D)
            coeff[(size_t)(r0 + row) * NC3D + m] = acc[q] + b2[m];
    }
}

// ---------------- host orchestration ----------------
extern "C" void kernel_launch(void* const* d_in, const int* in_sizes, int n_in,
                              void* d_out, int out_size) {
    const float* em   = (const float*)d_in[0];
    const float* eWih = (const float*)d_in[2];
    const float* eWhh = (const float*)d_in[3];
    const float* ebih = (const float*)d_in[4];
    const float* ebhh = (const float*)d_in[5];
    const float* muW  = (const float*)d_in[6];
    const float* mub  = (const float*)d_in[7];
    const float* lvW  = (const float*)d_in[8];
    const float* lvb  = (const float*)d_in[9];
    const float* zW   = (const float*)d_in[10];
    const float* zb   = (const float*)d_in[11];
    const float* dWih = (const float*)d_in[12];
    const float* dWhh = (const float*)d_in[13];
    const float* dbih = (const float*)d_in[14];
    const float* dbhh = (const float*)d_in[15];
    const float* m1W  = (const float*)d_in[16];
    const float* m1b  = (const float*)d_in[17];
    const float* m2W  = (const float*)d_in[18];
    const float* m2b  = (const float*)d_in[19];
    const float* oW   = (const float*)d_in[20];
    const float* ob   = (const float*)d_in[21];
    const float* c1W  = (const float*)d_in[22];
    const float* c1b  = (const float*)d_in[23];
    const float* c2W  = (const float*)d_in[24];
    const float* c2b  = (const float*)d_in[25];

    float* out   = (float*)d_out;
    float* pred  = out;
    float* coeff = out + 2400000;
    float* mu    = out + 2400000 + 5568000;
    float* lv    = mu + 491520;

    float *cbuf, *hF, *hy, *base, *m2, *encb;
    __nv_bfloat16 *hbf, *m1bf, *xbf, *ybf, *Benc, *Bdec, *Bm1, *Bm2;
    cudaGetSymbolAddress((void**)&cbuf, g_c);
    cudaGetSymbolAddress((void**)&hF,   g_hF);
    cudaGetSymbolAddress((void**)&hy,   g_hy);
    cudaGetSymbolAddress((void**)&base, g_base);
    cudaGetSymbolAddress((void**)&m2,   g_m2);
    cudaGetSymbolAddress((void**)&encb, g_encb);
    cudaGetSymbolAddress((void**)&hbf,  g_hbf);
    cudaGetSymbolAddress((void**)&m1bf, g_m1bf);
    cudaGetSymbolAddress((void**)&xbf,  g_xbf);
    cudaGetSymbolAddress((void**)&ybf,  g_ybf);
    cudaGetSymbolAddress((void**)&Benc, g_Benc);
    cudaGetSymbolAddress((void**)&Bdec, g_Bdec);
    cudaGetSymbolAddress((void**)&Bm1,  g_Bm1);
    cudaGetSymbolAddress((void**)&Bm2,  g_Bm2);
    const size_t HSZ = (size_t)BEFF * HID;
    const size_t XSL = (size_t)BEFF * 64;
    __nv_bfloat16* hbfp[2][2] = {{hbf, hbf + HSZ}, {hbf + 2 * HSZ, hbf + 3 * HSZ}};
    __nv_bfloat16* BencL = Benc + 8 * 9 * TILE_B_ELEMS;
    __nv_bfloat16* BdecL = Bdec + 8 * 9 * TILE_B_ELEMS;
    __nv_bfloat16* Bm1L = Bm1 + 2 * 8 * TILE_B_ELEMS;
    __nv_bfloat16* Bm2L = Bm2 + 2 * 8 * TILE_B_ELEMS;
    __nv_bfloat16* xlo = xbf + (size_t)WSTEPS * XSL;
    __nv_bfloat16* ylo = ybf + (size_t)(WSTEPS + 1) * XSL;

    cudaFuncSetAttribute(mma_kernel<9,1,0>, cudaFuncAttributeMaxDynamicSharedMemorySize, DYN_SMEM);
    cudaFuncSetAttribute(mma_kernel<8,0,1>, cudaFuncAttributeMaxDynamicSharedMemorySize, DYN_SMEM);
    cudaFuncSetAttribute(mma_kernel<8,0,2>, cudaFuncAttributeMaxDynamicSharedMemorySize, DYN_SMEM);

    const dim3 blk(256);
    // weight/input conversion (deterministic each call)
    convW_kernel<<<(8*9*2048+255)/256, blk>>>(eWhh, 512, 512, 1, eWih, 25, 25, 8, 9, Benc, BencL);
    convW_kernel<<<(8*9*2048+255)/256, blk>>>(dWhh, 512, 512, 1, dWih + 512, 537, 25, 8, 9, Bdec, BdecL);
    convW_kernel<<<(2*8*2048+255)/256, blk>>>(m1W, 512, 512, 0, nullptr, 0, 0, 2, 8, Bm1, Bm1L);
    convW_kernel<<<(2*8*2048+255)/256, blk>>>(m2W, 512, 512, 0, nullptr, 0, 0, 2, 8, Bm2, Bm2L);
    convX_kernel<<<(WSTEPS*BEFF*64+255)/256, blk>>>(em, xbf, xlo);
    addvec_kernel<<<8, blk>>>(ebih, ebhh, encb, GATES);
    // zero c + h bf16 buf0 (hi+lo)
    zero_u4<<<256, blk>>>((uint4*)cbuf, (int)(HSZ / 4));
    zero_u4<<<256, blk>>>((uint4*)hbfp[0][0], (int)(HSZ / 8));
    zero_u4<<<256, blk>>>((uint4*)hbfp[0][1], (int)(HSZ / 8));

    // ---- encoder ----
    for (int t = 0; t < WSTEPS; t++) {
        int s = t & 1, d = s ^ 1;
        mma_kernel<9,1,0><<<dim3(15, 8), 256, DYN_SMEM>>>(
            hbfp[s][0], hbfp[s][1], xbf + (size_t)t * XSL, xlo + (size_t)t * XSL,
            Benc, BencL, encb, 0, nullptr, cbuf, hF, hbfp[d][0], hbfp[d][1], nullptr);
    }

    // ---- latent head ----
    gemm_kernel<0><<<dim3(30, 4), blk>>>(hF, HID, muW, HID, mub, nullptr, mu, ZDIM, ZDIM, HID);
    gemm_kernel<0><<<dim3(30, 4), blk>>>(hF, HID, lvW, HID, lvb, nullptr, lv, ZDIM, ZDIM, HID);
    gemm_kernel<0><<<dim3(30, 8), blk>>>(mu, ZDIM, zW, ZDIM, zb, nullptr, hy, HID, HID, ZDIM);
    gemm_kernel<0><<<dim3(30, 32), blk>>>(hy, HID, dWih, HID + FEAT, dbih, dbhh,
                                          base, GATES, GATES, HID);

    // reset state for decoder
    zero_u4<<<256, blk>>>((uint4*)cbuf, (int)(HSZ / 4));
    zero_u4<<<256, blk>>>((uint4*)hbfp[0][0], (int)(HSZ / 8));
    zero_u4<<<256, blk>>>((uint4*)hbfp[0][1], (int)(HSZ / 8));

    // ---- decoder ----
    for (int t = 0; t < WSTEPS; t++) {
        int s = t & 1, d = s ^ 1;
        const __nv_bfloat16* yh = (t == 0) ? (ybf + (size_t)WSTEPS * XSL) : (ybf + (size_t)(t - 1) * XSL);
        const __nv_bfloat16* yl = (t == 0) ? (ylo + (size_t)WSTEPS * XSL) : (ylo + (size_t)(t - 1) * XSL);
        mma_kernel<9,1,0><<<dim3(15, 8), 256, DYN_SMEM>>>(
            hbfp[s][0], hbfp[s][1], yh, yl,
            Bdec, BdecL, base, GATES, nullptr, cbuf, hF, hbfp[d][0], hbfp[d][1], nullptr);
        mma_kernel<8,0,1><<<dim3(15, 2), 256, DYN_SMEM>>>(
            hbfp[d][0], hbfp[d][1], nullptr, nullptr,
            Bm1, Bm1L, nullptr, 0, m1b, nullptr, nullptr, m1bf, m1bf + HSZ, nullptr);
        mma_kernel<8,0,2><<<dim3(15, 2), 256, DYN_SMEM>>>(
            m1bf, m1bf + HSZ, nullptr, nullptr,
            Bm2, Bm2L, nullptr, 0, m2b, nullptr, nullptr, nullptr, nullptr, m2);
        outproj_kernel<<<30, blk>>>(m2, oW, ob, pred + t * FEAT,
                                    ybf + (size_t)t * XSL, ylo + (size_t)t * XSL);
    }

    // ---- 3DMM head ----
    head3dmm_kernel<<<1500, blk>>>(pred, c1W, c1b, c2W, c2b, coeff);
}

// round 12
// speedup vs baseline: 1.5563x; 1.0035x over previous
#include <cuda_runtime.h>
#include <cuda_bf16.h>
#include <math.h>
#include <stdint.h>

#define BEFF   1920
#define HID    512
#define FEAT   25
#define ZDIM   256
#define MDIM   512
#define NC3D   58
#define WSTEPS 50
#define GATES  2048

#define TILE_A_BYTES 16384              // 128 rows x 128 B
#define TILE_B_BYTES 32768              // 256 rows x 128 B
#define TILE_B_ELEMS 16384
#define BUF_BYTES (2*TILE_A_BYTES + 2*TILE_B_BYTES)   // 98304
#define DYN_SMEM (2*BUF_BYTES)                         // 196608

// ---------------- device scratch ----------------
__device__ float g_c[BEFF * HID];
__device__ float g_hF[BEFF * HID];
__device__ float g_hy[BEFF * HID];
__device__ float g_base[BEFF * GATES];
__device__ float g_m2[BEFF * MDIM];
__device__ float g_encb[GATES];
__device__ __align__(256) __nv_bfloat16 g_hbf[2][2][BEFF * HID];
__device__ __align__(256) __nv_bfloat16 g_m1bf[2][BEFF * MDIM];
__device__ __align__(256) __nv_bfloat16 g_xbf[2][WSTEPS * BEFF * 64];
__device__ __align__(256) __nv_bfloat16 g_ybf[2][(WSTEPS + 1) * BEFF * 64]; // slot WSTEPS stays 0
__device__ __align__(256) __nv_bfloat16 g_Benc[2][8 * 9 * TILE_B_ELEMS];
__device__ __align__(256) __nv_bfloat16 g_Bdec[2][8 * 9 * TILE_B_ELEMS];
__device__ __align__(256) __nv_bfloat16 g_Bm1[2][2 * 8 * TILE_B_ELEMS];
__device__ __align__(256) __nv_bfloat16 g_Bm2[2][2 * 8 * TILE_B_ELEMS];

// ---------------- helpers ----------------
__device__ __forceinline__ float sigf(float x) { return 1.0f / (1.0f + __expf(-x)); }
__device__ __forceinline__ uint32_t s2u(const void* p) {
    return (uint32_t)__cvta_generic_to_shared(p);
}
__device__ __forceinline__ void cpa4(uint32_t d, const void* s) {
    asm volatile("cp.async.ca.shared.global [%0], [%1], 4;" :: "r"(d), "l"(s));
}
__device__ __forceinline__ void cpa4p(uint32_t d, const void* s, int sz) {
    asm volatile("cp.async.ca.shared.global [%0], [%1], 4, %2;" :: "r"(d), "l"(s), "r"(sz));
}
__device__ __forceinline__ void cpa16(uint32_t d, const void* s) {
    asm volatile("cp.async.cg.shared.global [%0], [%1], 16;" :: "r"(d), "l"(s));
}
__device__ __forceinline__ void cp_commit() { asm volatile("cp.async.commit_group;"); }
__device__ __forceinline__ void cp_wait0()  { asm volatile("cp.async.wait_group 0;"); }
__device__ __forceinline__ void cp_wait1()  { asm volatile("cp.async.wait_group 1;"); }

#define SWZ(o) ((o) ^ (((o) >> 3) & 0x70))

#define LDM_X4(r, a) \
    asm volatile("ldmatrix.sync.aligned.m8n8.x4.shared.b16 {%0,%1,%2,%3}, [%4];" \
        : "=r"((r)[0]), "=r"((r)[1]), "=r"((r)[2]), "=r"((r)[3]) : "r"(a))

#define MMA16816(d, a, b) \
    asm volatile("mma.sync.aligned.m16n8k16.row.col.f32.bf16.bf16.f32 " \
        "{%0,%1,%2,%3}, {%4,%5,%6,%7}, {%8,%9}, {%0,%1,%2,%3};" \
        : "+f"((d)[0]), "+f"((d)[1]), "+f"((d)[2]), "+f"((d)[3]) \
        : "r"((a)[0]), "r"((a)[1]), "r"((a)[2]), "r"((a)[3]), "r"((b)[0]), "r"((b)[1]))

// ---------------- fused init kernels (2 launches so ncu -s 5 hits mma_kernel) --
__device__ __forceinline__ void conv_unit(int u, const float* W, int ldw, int Kmain,
                                          int gateBlocked, const float* Wx, int ldx, int Kx,
                                          int nCh,
                                          __nv_bfloat16* outHi, __nv_bfloat16* outLo) {
    int bn = u / (nCh * 2048);
    int rem = u - bn * nCh * 2048;
    int c = rem / 2048;
    int unit = rem & 2047;
    int r = unit >> 3, c16 = unit & 7;
    int srow = gateBlocked ? ((r >> 6) * HID + bn * 64 + (r & 63)) : (bn * 256 + r);
    bool xc = (Wx != nullptr) && (c == nCh - 1);
    unsigned short hb[8], lb[8];
#pragma unroll
    for (int e = 0; e < 8; e++) {
        int k = c16 * 8 + e;
        float v;
        if (xc) v = (k < Kx) ? Wx[(size_t)srow * ldx + k] : 0.0f;
        else {
            int kk = c * 64 + k;
            v = (kk < Kmain) ? W[(size_t)srow * ldw + kk] : 0.0f;
        }
        __nv_bfloat16 h = __float2bfloat16(v);
        hb[e] = __bfloat16_as_ushort(h);
        lb[e] = __bfloat16_as_ushort(__float2bfloat16(v - __bfloat162float(h)));
    }
    uint32_t so = SWZ((uint32_t)(r * 128 + c16 * 16));
    size_t dstu = (size_t)(bn * nCh + c) * 2048 + (so >> 4);
    uint4 vh, vl;
    vh.x = hb[0] | (hb[1] << 16); vh.y = hb[2] | (hb[3] << 16);
    vh.z = hb[4] | (hb[5] << 16); vh.w = hb[6] | (hb[7] << 16);
    vl.x = lb[0] | (lb[1] << 16); vl.y = lb[2] | (lb[3] << 16);
    vl.z = lb[4] | (lb[5] << 16); vl.w = lb[6] | (lb[7] << 16);
    ((uint4*)outHi)[dstu] = vh;
    ((uint4*)outLo)[dstu] = vl;
}

__global__ void convAll_kernel(const float* eWhh, const float* eWih,
                               const float* dWhh, const float* dWih512,
                               const float* m1W, const float* m2W,
                               __nv_bfloat16* Benc, __nv_bfloat16* BencL,
                               __nv_bfloat16* Bdec, __nv_bfloat16* BdecL,
                               __nv_bfloat16* Bm1, __nv_bfloat16* Bm1L,
                               __nv_bfloat16* Bm2, __nv_bfloat16* Bm2L) {
    const int ENC_U = 8 * 9 * 2048;   // 147456
    const int MLP_U = 2 * 8 * 2048;   // 32768
    const int total = 2 * ENC_U + 2 * MLP_U;
    for (int u = blockIdx.x * blockDim.x + threadIdx.x; u < total;
         u += gridDim.x * blockDim.x) {
        if (u < ENC_U)
            conv_unit(u, eWhh, 512, 512, 1, eWih, 25, 25, 9, Benc, BencL);
        else if (u < 2 * ENC_U)
            conv_unit(u - ENC_U, dWhh, 512, 512, 1, dWih512, 537, 25, 9, Bdec, BdecL);
        else if (u < 2 * ENC_U + MLP_U)
            conv_unit(u - 2 * ENC_U, m1W, 512, 512, 0, nullptr, 0, 0, 8, Bm1, Bm1L);
        else
            conv_unit(u - 2 * ENC_U - MLP_U, m2W, 512, 512, 0, nullptr, 0, 0, 8, Bm2, Bm2L);
    }
}

// zeros (c, h-hi, h-lo) + x conversion + enc bias add, one launch
__global__ void prep_kernel(const float* __restrict__ em,
                            __nv_bfloat16* __restrict__ xhi, __nv_bfloat16* __restrict__ xlo,
                            const float* __restrict__ b1, const float* __restrict__ b2,
                            float* __restrict__ encb,
                            uint4* __restrict__ zc, uint4* __restrict__ zh0,
                            uint4* __restrict__ zh1) {
    const int NZC = BEFF * HID / 4;        // 245760 uint4
    const int NZH = BEFF * HID / 8;        // 122880 uint4 (bf16 buffer)
    const int NCX = WSTEPS * BEFF * 64;    // 6144000
    const int total = NZC + 2 * NZH + NCX + GATES;
    uint4 z = {0, 0, 0, 0};
    for (int u = blockIdx.x * blockDim.x + threadIdx.x; u < total;
         u += gridDim.x * blockDim.x) {
        if (u < NZC) { zc[u] = z; }
        else if (u < NZC + NZH) { zh0[u - NZC] = z; }
        else if (u < NZC + 2 * NZH) { zh1[u - NZC - NZH] = z; }
        else if (u < NZC + 2 * NZH + NCX) {
            int idx = u - (NZC + 2 * NZH);
            int t = idx / (BEFF * 64);
            int rem = idx - t * BEFF * 64;
            int i = rem >> 6, k = rem & 63;
            float v = (k < FEAT) ? em[(size_t)i * 1250 + t * FEAT + k] : 0.0f;
            __nv_bfloat16 h = __float2bfloat16(v);
            xhi[idx] = h;
            xlo[idx] = __float2bfloat16(v - __bfloat162float(h));
        } else {
            int i = u - (NZC + 2 * NZH + NCX);
            encb[i] = b1[i] + b2[i];
        }
    }
}

// decoder state reset in one launch
__global__ void zero3_kernel(uint4* __restrict__ zc, uint4* __restrict__ zh0,
                             uint4* __restrict__ zh1) {
    const int NZC = BEFF * HID / 4;
    const int NZH = BEFF * HID / 8;
    const int total = NZC + 2 * NZH;
    uint4 z = {0, 0, 0, 0};
    for (int u = blockIdx.x * blockDim.x + threadIdx.x; u < total;
         u += gridDim.x * blockDim.x) {
        if (u < NZC) zc[u] = z;
        else if (u < NZC + NZH) zh0[u - NZC] = z;
        else zh1[u - NZC - NZH] = z;
    }
}

// ---------------- SIMT GEMM (small shapes) ----------------
template <int ACT>
__global__ void __launch_bounds__(256, 2)
gemm_kernel(const float* __restrict__ A, int lda,
            const float* __restrict__ W, int ldw,
            const float* __restrict__ b1, const float* __restrict__ b2,
            float* __restrict__ C, int ldc, int N, int K) {
    __shared__ __align__(16) float As[2][16][68];
    __shared__ __align__(16) float Bs[2][16][68];
    const int tid = threadIdx.x;
    const int tx = tid & 15, ty = tid >> 4;
    const int n0 = blockIdx.x * 64, m0 = blockIdx.y * 64;
    const int lk = tid & 15, lr = tid >> 4;
    float acc[4][4] = {};
    const int nch = K >> 4;
    auto issue = [&](int k0, int b) {
#pragma unroll
        for (int i = 0; i < 4; i++) {
            const int row = lr + 16 * i;
            cpa4(s2u(&As[b][lk][row]), &A[(size_t)(n0 + row) * lda + k0 + lk]);
            const int m = m0 + row;
            const int mc = (m < N) ? m : 0;
            cpa4p(s2u(&Bs[b][lk][row]), &W[(size_t)mc * ldw + k0 + lk], (m < N) ? 4 : 0);
        }
        cp_commit();
    };
    issue(0, 0);
    for (int c = 0; c < nch; c++) {
        if (c + 1 < nch) { issue((c + 1) * 16, (c + 1) & 1); cp_wait1(); }
        else             { cp_wait0(); }
        __syncthreads();
        const int p = c & 1;
#pragma unroll
        for (int kk = 0; kk < 16; kk++) {
            float4 a4 = *(const float4*)&As[p][kk][ty * 4];
            float4 b4 = *(const float4*)&Bs[p][kk][tx * 4];
            float av[4] = {a4.x, a4.y, a4.z, a4.w};
            float bv[4] = {b4.x, b4.y, b4.z, b4.w};
#pragma unroll
            for (int r = 0; r < 4; r++)
#pragma unroll
                for (int c2 = 0; c2 < 4; c2++)
                    acc[r][c2] += av[r] * bv[c2];
        }
        __syncthreads();
    }
#pragma unroll
    for (int r = 0; r < 4; r++) {
        const int n = n0 + ty * 4 + r;
#pragma unroll
        for (int c2 = 0; c2 < 4; c2++) {
            const int m = m0 + tx * 4 + c2;
            if (m < N) {
                float v = acc[r][c2];
                if (b1) v += b1[m];
                if (b2) v += b2[m];
                if (ACT == 1) v = tanhf(v);
                C[(size_t)n * ldc + m] = v;
            }
        }
    }
}

// out projection (N=25) + bf16 hi/lo y emit for decoder recurrence
__global__ void __launch_bounds__(256, 2)
outproj_kernel(const float* __restrict__ A, const float* __restrict__ W,
               const float* __restrict__ b, float* __restrict__ pred,
               __nv_bfloat16* __restrict__ yhi, __nv_bfloat16* __restrict__ ylo) {
    __shared__ __align__(16) float As[2][16][68];
    __shared__ __align__(16) float Bs[2][16][68];
    const int tid = threadIdx.x;
    const int tx = tid & 15, ty = tid >> 4;
    const int n0 = blockIdx.x * 64;
    const int lk = tid & 15, lr = tid >> 4;
    float acc[4][4] = {};
    auto issue = [&](int k0, int bb) {
#pragma unroll
        for (int i = 0; i < 4; i++) {
            const int row = lr + 16 * i;
            cpa4(s2u(&As[bb][lk][row]), &A[(size_t)(n0 + row) * MDIM + k0 + lk]);
            const int mc = (row < FEAT) ? row : 0;
            cpa4p(s2u(&Bs[bb][lk][row]), &W[(size_t)mc * MDIM + k0 + lk], (row < FEAT) ? 4 : 0);
        }
        cp_commit();
    };
    issue(0, 0);
    for (int c = 0; c < 32; c++) {
        if (c + 1 < 32) { issue((c + 1) * 16, (c + 1) & 1); cp_wait1(); }
        else            { cp_wait0(); }
        __syncthreads();
        const int p = c & 1;
#pragma unroll
        for (int kk = 0; kk < 16; kk++) {
            float4 a4 = *(const float4*)&As[p][kk][ty * 4];
            float4 b4 = *(const float4*)&Bs[p][kk][tx * 4];
            float av[4] = {a4.x, a4.y, a4.z, a4.w};
            float bv[4] = {b4.x, b4.y, b4.z, b4.w};
#pragma unroll
            for (int r = 0; r < 4; r++)
#pragma unroll
                for (int c2 = 0; c2 < 4; c2++)
                    acc[r][c2] += av[r] * bv[c2];
        }
        __syncthreads();
    }
#pragma unroll
    for (int r = 0; r < 4; r++) {
        const int n = n0 + ty * 4 + r;
#pragma unroll
        for (int c2 = 0; c2 < 4; c2++) {
            const int m = tx * 4 + c2;
            if (m < FEAT) {
                float v = acc[r][c2] + b[m];
                pred[(size_t)n * 1250 + m] = v;
                __nv_bfloat16 h = __float2bfloat16(v);
                yhi[(size_t)n * 64 + m] = h;
                ylo[(size_t)n * 64 + m] = __float2bfloat16(v - __bfloat162float(h));
            }
        }
    }
}

// ---------------- mma.sync GEMM (bf16 3-term split) ----------------
// CTA: 128 batch rows x 256 cols. 256 threads = 8 warps (2 M x 4 N), warp tile 64x64.
// B fragments double-buffered across pr to hide ldmatrix latency.
// EPI: 0 = LSTM cell, 1 = tanh -> bf16 hi/lo, 2 = tanh -> fp32
template <int NCH, int HASX, int EPI>
__global__ void __launch_bounds__(256)
mma_kernel(const __nv_bfloat16* __restrict__ ahi, const __nv_bfloat16* __restrict__ alo,
           const __nv_bfloat16* __restrict__ xhi, const __nv_bfloat16* __restrict__ xlo,
           const __nv_bfloat16* __restrict__ Bth, const __nv_bfloat16* __restrict__ Btl,
           const float* __restrict__ base, int base_stride,
           const float* __restrict__ bias,
           float* __restrict__ c_io, float* __restrict__ hF,
           __nv_bfloat16* __restrict__ ohi, __nv_bfloat16* __restrict__ olo,
           float* __restrict__ outF) {
    extern __shared__ __align__(1024) char smem[];
    const int tid = threadIdx.x;
    const int wid = tid >> 5;
    const int lane = tid & 31;
    const int n0 = blockIdx.x * 128;
    const int bn = blockIdx.y;
    const int wm = wid & 1;        // M block (64 rows)
    const int wn = wid >> 1;       // N block (64 cols)
    const int ldAmain = (NCH - HASX) * 128;   // bytes per A row

    float acc[4][8][4] = {};       // [mi 16-row][n8 group][frag]

    auto do_copy = [&](int c, int p) {
        char* bb = smem + p * BUF_BYTES;
        uint32_t sAh = s2u(bb), sAl = sAh + TILE_A_BYTES;
        uint32_t sBh = sAh + 2 * TILE_A_BYTES, sBl = sBh + TILE_B_BYTES;
        const char *ap, *alp; int ld;
        if (HASX && c == NCH - 1) { ap = (const char*)xhi; alp = (const char*)xlo; ld = 128; }
        else { ap = (const char*)ahi + c * 128; alp = (const char*)alo + c * 128; ld = ldAmain; }
#pragma unroll
        for (int i = 0; i < 4; i++) {
            int u = tid + i * 256;         // 1024 units of 16B for 128x128B tile
            int r = u >> 3, c16 = u & 7;
            uint32_t so = SWZ((uint32_t)(r * 128 + c16 * 16));
            cpa16(sAh + so, ap + (size_t)(n0 + r) * ld + c16 * 16);
            cpa16(sAl + so, alp + (size_t)(n0 + r) * ld + c16 * 16);
        }
        const char* bh = (const char*)Bth + (size_t)(bn * NCH + c) * TILE_B_BYTES;
        const char* bl = (const char*)Btl + (size_t)(bn * NCH + c) * TILE_B_BYTES;
#pragma unroll
        for (int i = 0; i < 8; i++) {
            int u = tid + i * 256;         // 2048 units
            cpa16(sBh + u * 16, bh + (size_t)u * 16);
            cpa16(sBl + u * 16, bl + (size_t)u * 16);
        }
        cp_commit();
    };

    do_copy(0, 0);
    if (NCH > 1) do_copy(1, 1);
    for (int c = 0; c < NCH; c++) {
        const int p = c & 1;
        if (c + 1 < NCH) cp_wait1(); else cp_wait0();
        __syncthreads();
        uint32_t baseu = s2u(smem + p * BUF_BYTES);
        uint32_t aHb = baseu, aLb = baseu + TILE_A_BYTES;
        uint32_t bHb = baseu + 2 * TILE_A_BYTES, bLb = bHb + TILE_B_BYTES;
#pragma unroll
        for (int ks = 0; ks < 4; ks++) {
            uint32_t ah[4][4], al[4][4];
#pragma unroll
            for (int mi = 0; mi < 4; mi++) {
                int rowA = wm * 64 + mi * 16 + (lane & 15);
                uint32_t off = SWZ((uint32_t)(rowA * 128 + ks * 32 + (lane >> 4) * 16));
                LDM_X4(ah[mi], aHb + off);
                LDM_X4(al[mi], aLb + off);
            }
            // B fragment double buffer across pr
            uint32_t bh[2][4], bl[2][4];
            {
                int rowB = wn * 64 + ((lane >> 4) << 3) + (lane & 7);
                uint32_t offB = SWZ((uint32_t)(rowB * 128 + ks * 32 + ((lane >> 3) & 1) * 16));
                LDM_X4(bh[0], bHb + offB);
                LDM_X4(bl[0], bLb + offB);
            }
#pragma unroll
            for (int pr = 0; pr < 4; pr++) {
                const int cur = pr & 1, nxt = cur ^ 1;
                if (pr < 3) {
                    int rowB = wn * 64 + (pr + 1) * 16 + ((lane >> 4) << 3) + (lane & 7);
                    uint32_t offB = SWZ((uint32_t)(rowB * 128 + ks * 32 + ((lane >> 3) & 1) * 16));
                    LDM_X4(bh[nxt], bHb + offB);
                    LDM_X4(bl[nxt], bLb + offB);
                }
#pragma unroll
                for (int mi = 0; mi < 4; mi++) {
#pragma unroll
                    for (int t2 = 0; t2 < 2; t2++) {
                        float* d = acc[mi][pr * 2 + t2];
                        MMA16816(d, ah[mi], bh[cur] + t2 * 2);
                        MMA16816(d, ah[mi], bl[cur] + t2 * 2);
                        MMA16816(d, al[mi], bh[cur] + t2 * 2);
                    }
                }
            }
        }
        __syncthreads();
        if (c + 2 < NCH) do_copy(c + 2, p);
    }

    // stage accumulators to smem: sAcc[128][256] fp32 (128 KB)
    float* sAcc = (float*)smem;
#pragma unroll
    for (int mi = 0; mi < 4; mi++) {
#pragma unroll
        for (int ni = 0; ni < 8; ni++) {
            int row = wm * 64 + mi * 16 + (lane >> 2);
            int col = wn * 64 + ni * 8 + 2 * (lane & 3);
            *(float2*)&sAcc[row * 256 + col] = make_float2(acc[mi][ni][0], acc[mi][ni][1]);
            *(float2*)&sAcc[(row + 8) * 256 + col] = make_float2(acc[mi][ni][2], acc[mi][ni][3]);
        }
    }
    __syncthreads();

    const int rgrp = tid >> 6;       // 0..3
    const int col = tid & 63;        // 0..63 (consecutive per warp -> coalesced)
    if (EPI == 0) {
        const int j0 = bn * 64;
        const int j = j0 + col;
#pragma unroll 4
        for (int rr = 0; rr < 32; rr++) {
            int row = rr * 4 + rgrp;
            int n = n0 + row;
            const float* bp = base + (size_t)n * base_stride;
            float iv = sAcc[row * 256 + col]       + bp[j];
            float fv = sAcc[row * 256 + 64 + col]  + bp[512 + j];
            float gv = sAcc[row * 256 + 128 + col] + bp[1024 + j];
            float ov = sAcc[row * 256 + 192 + col] + bp[1536 + j];
            float cold = c_io[(size_t)n * HID + j];
            float cn = sigf(fv) * cold + sigf(iv) * tanhf(gv);
            float hn = sigf(ov) * tanhf(cn);
            c_io[(size_t)n * HID + j] = cn;
            hF[(size_t)n * HID + j] = hn;
            __nv_bfloat16 h = __float2bfloat16(hn);
            ohi[(size_t)n * HID + j] = h;
            olo[(size_t)n * HID + j] = __float2bfloat16(hn - __bfloat162float(h));
        }
    } else {
#pragma unroll 2
        for (int rr = 0; rr < 32; rr++) {
            int row = rr * 4 + rgrp;
            int n = n0 + row;
#pragma unroll
            for (int cg = 0; cg < 4; cg++) {
                int colx = cg * 64 + col;
                int gcol = bn * 256 + colx;
                float v = tanhf(sAcc[row * 256 + colx] + bias[gcol]);
                if (EPI == 2) {
                    outF[(size_t)n * MDIM + gcol] = v;
                } else {
                    __nv_bfloat16 h = __float2bfloat16(v);
                    ohi[(size_t)n * MDIM + gcol] = h;
                    olo[(size_t)n * MDIM + gcol] = __float2bfloat16(v - __bfloat162float(h));
                }
            }
        }
    }
}

// ---------------- fused 3DMM head ----------------
__global__ void __launch_bounds__(256)
head3dmm_kernel(const float* __restrict__ pred,
                const float* __restrict__ C1, const float* __restrict__ b1,
                const float* __restrict__ C2, const float* __restrict__ b2,
                float* __restrict__ coeff) {
    __shared__ __align__(16) float sP[64][FEAT + 1];
    __shared__ __align__(16) float sC1c[64][FEAT + 1];
    __shared__ __align__(16) float sHid[64][64];
    const int tid = threadIdx.x;
    const int r0 = blockIdx.x * 64;
    for (int i = tid; i < 64 * FEAT; i += 256)
        sP[i / FEAT][i % FEAT] = pred[(size_t)(r0 + i / FEAT) * FEAT + i % FEAT];
    const int row = tid >> 2;
    const int l4 = tid & 3;
    float acc[15];
#pragma unroll
    for (int q = 0; q < 15; q++) acc[q] = 0.0f;
    for (int jc = 0; jc < HID; jc += 64) {
        __syncthreads();
        for (int i = tid; i < 64 * FEAT; i += 256)
            sC1c[i / FEAT][i % FEAT] = C1[(size_t)(jc + i / FEAT) * FEAT + i % FEAT];
        __syncthreads();
#pragma unroll
        for (int jj = 0; jj < 16; jj++) {
            const int jl = l4 * 16 + jj;
            float v = b1[jc + jl];
#pragma unroll
            for (int k = 0; k < FEAT; k++)
                v += sP[row][k] * sC1c[jl][k];
            sHid[row][jl] = tanhf(v);
        }
        __syncthreads();
        for (int q = 0; q < 15; q++) {
            const int m = l4 + q * 4;
            if (m < NC3D) {
                float s = 0.0f;
                const float* c2r = C2 + (size_t)m * HID + jc;
#pragma unroll
                for (int jj = 0; jj < 64; jj++)
                    s += sHid[row][jj] * c2r[jj];
                acc[q] += s;
            }
        }
    }
#pragma unroll
    for (int q = 0; q < 15; q++) {
        const int m = l4 + q * 4;
        if (m < NC3D)
            coeff[(size_t)(r0 + row) * NC3D + m] = acc[q] + b2[m];
    }
}

// ---------------- host orchestration ----------------
extern "C" void kernel_launch(void* const* d_in, const int* in_sizes, int n_in,
                              void* d_out, int out_size) {
    const float* em   = (const float*)d_in[0];
    const float* eWih = (const float*)d_in[2];
    const float* eWhh = (const float*)d_in[3];
    const float* ebih = (const float*)d_in[4];
    const float* ebhh = (const float*)d_in[5];
    const float* muW  = (const float*)d_in[6];
    const float* mub  = (const float*)d_in[7];
    const float* lvW  = (const float*)d_in[8];
    const float* lvb  = (const float*)d_in[9];
    const float* zW   = (const float*)d_in[10];
    const float* zb   = (const float*)d_in[11];
    const float* dWih = (const float*)d_in[12];
    const float* dWhh = (const float*)d_in[13];
    const float* dbih = (const float*)d_in[14];
    const float* dbhh = (const float*)d_in[15];
    const float* m1W  = (const float*)d_in[16];
    const float* m1b  = (const float*)d_in[17];
    const float* m2W  = (const float*)d_in[18];
    const float* m2b  = (const float*)d_in[19];
    const float* oW   = (const float*)d_in[20];
    const float* ob   = (const float*)d_in[21];
    const float* c1W  = (const float*)d_in[22];
    const float* c1b  = (const float*)d_in[23];
    const float* c2W  = (const float*)d_in[24];
    const float* c2b  = (const float*)d_in[25];

    float* out   = (float*)d_out;
    float* pred  = out;
    float* coeff = out + 2400000;
    float* mu    = out + 2400000 + 5568000;
    float* lv    = mu + 491520;

    float *cbuf, *hF, *hy, *base, *m2, *encb;
    __nv_bfloat16 *hbf, *m1bf, *xbf, *ybf, *Benc, *Bdec, *Bm1, *Bm2;
    cudaGetSymbolAddress((void**)&cbuf, g_c);
    cudaGetSymbolAddress((void**)&hF,   g_hF);
    cudaGetSymbolAddress((void**)&hy,   g_hy);
    cudaGetSymbolAddress((void**)&base, g_base);
    cudaGetSymbolAddress((void**)&m2,   g_m2);
    cudaGetSymbolAddress((void**)&encb, g_encb);
    cudaGetSymbolAddress((void**)&hbf,  g_hbf);
    cudaGetSymbolAddress((void**)&m1bf, g_m1bf);
    cudaGetSymbolAddress((void**)&xbf,  g_xbf);
    cudaGetSymbolAddress((void**)&ybf,  g_ybf);
    cudaGetSymbolAddress((void**)&Benc, g_Benc);
    cudaGetSymbolAddress((void**)&Bdec, g_Bdec);
    cudaGetSymbolAddress((void**)&Bm1,  g_Bm1);
    cudaGetSymbolAddress((void**)&Bm2,  g_Bm2);
    const size_t HSZ = (size_t)BEFF * HID;
    const size_t XSL = (size_t)BEFF * 64;
    __nv_bfloat16* hbfp[2][2] = {{hbf, hbf + HSZ}, {hbf + 2 * HSZ, hbf + 3 * HSZ}};
    __nv_bfloat16* BencL = Benc + 8 * 9 * TILE_B_ELEMS;
    __nv_bfloat16* BdecL = Bdec + 8 * 9 * TILE_B_ELEMS;
    __nv_bfloat16* Bm1L = Bm1 + 2 * 8 * TILE_B_ELEMS;
    __nv_bfloat16* Bm2L = Bm2 + 2 * 8 * TILE_B_ELEMS;
    __nv_bfloat16* xlo = xbf + (size_t)WSTEPS * XSL;
    __nv_bfloat16* ylo = ybf + (size_t)(WSTEPS + 1) * XSL;

    cudaFuncSetAttribute(mma_kernel<9,1,0>, cudaFuncAttributeMaxDynamicSharedMemorySize, DYN_SMEM);
    cudaFuncSetAttribute(mma_kernel<8,0,1>, cudaFuncAttributeMaxDynamicSharedMemorySize, DYN_SMEM);
    cudaFuncSetAttribute(mma_kernel<8,0,2>, cudaFuncAttributeMaxDynamicSharedMemorySize, DYN_SMEM);

    const dim3 blk(256);
    // launch 1: all weight conversions
    convAll_kernel<<<1408, blk>>>(eWhh, eWih, dWhh, dWih + 512, m1W, m2W,
                                  Benc, BencL, Bdec, BdecL, Bm1, Bm1L, Bm2, Bm2L);
    // launch 2: zeros + x conversion + enc bias
    prep_kernel<<<2048, blk>>>(em, xbf, xlo, ebih, ebhh, encb,
                               (uint4*)cbuf, (uint4*)hbfp[0][0], (uint4*)hbfp[0][1]);

    // ---- encoder (launches 3..52 — ncu -s 5 -c 1 lands here) ----
    for (int t = 0; t < WSTEPS; t++) {
        int s = t & 1, d = s ^ 1;
        mma_kernel<9,1,0><<<dim3(15, 8), 256, DYN_SMEM>>>(
            hbfp[s][0], hbfp[s][1], xbf + (size_t)t * XSL, xlo + (size_t)t * XSL,
            Benc, BencL, encb, 0, nullptr, cbuf, hF, hbfp[d][0], hbfp[d][1], nullptr);
    }

    // ---- latent head ----
    gemm_kernel<0><<<dim3(30, 4), blk>>>(hF, HID, muW, HID, mub, nullptr, mu, ZDIM, ZDIM, HID);
    gemm_kernel<0><<<dim3(30, 4), blk>>>(hF, HID, lvW, HID, lvb, nullptr, lv, ZDIM, ZDIM, HID);
    gemm_kernel<0><<<dim3(30, 8), blk>>>(mu, ZDIM, zW, ZDIM, zb, nullptr, hy, HID, HID, ZDIM);
    gemm_kernel<0><<<dim3(30, 32), blk>>>(hy, HID, dWih, HID + FEAT, dbih, dbhh,
                                          base, GATES, GATES, HID);

    // reset state for decoder (1 launch)
    zero3_kernel<<<512, blk>>>((uint4*)cbuf, (uint4*)hbfp[0][0], (uint4*)hbfp[0][1]);

    // ---- decoder ----
    for (int t = 0; t < WSTEPS; t++) {
        int s = t & 1, d = s ^ 1;
        const __nv_bfloat16* yh = (t == 0) ? (ybf + (size_t)WSTEPS * XSL) : (ybf + (size_t)(t - 1) * XSL);
        const __nv_bfloat16* yl = (t == 0) ? (ylo + (size_t)WSTEPS * XSL) : (ylo + (size_t)(t - 1) * XSL);
        mma_kernel<9,1,0><<<dim3(15, 8), 256, DYN_SMEM>>>(
            hbfp[s][0], hbfp[s][1], yh, yl,
            Bdec, BdecL, base, GATES, nullptr, cbuf, hF, hbfp[d][0], hbfp[d][1], nullptr);
        mma_kernel<8,0,1><<<dim3(15, 2), 256, DYN_SMEM>>>(
            hbfp[d][0], hbfp[d][1], nullptr, nullptr,
            Bm1, Bm1L, nullptr, 0, m1b, nullptr, nullptr, m1bf, m1bf + HSZ, nullptr);
        mma_kernel<8,0,2><<<dim3(15, 2), 256, DYN_SMEM>>>(
            m1bf, m1bf + HSZ, nullptr, nullptr,
            Bm2, Bm2L, nullptr, 0, m2b, nullptr, nullptr, nullptr, nullptr, m2);
        outproj_kernel<<<30, blk>>>(m2, oW, ob, pred + t * FEAT,
                                    ybf + (size_t)t * XSL, ylo + (size_t)t * XSL);
    }

    // ---- 3DMM head ----
    head3dmm_kernel<<<1500, blk>>>(pred, c1W, c1b, c2W, c2b, coeff);
}

// round 13
// speedup vs baseline: 1.9336x; 1.2424x over previous
#include <cuda_runtime.h>
#include <cuda_bf16.h>
#include <math.h>
#include <stdint.h>

#define BEFF   1920
#define HID    512
#define FEAT   25
#define ZDIM   256
#define MDIM   512
#define NC3D   58
#define WSTEPS 50
#define GATES  2048

// tile config: TM=64 rows x TN=128 cols, chunks of K=64
#define TILE_A_BYTES 8192               // 64 rows x 128 B
#define TILE_B_BYTES 16384              // 128 rows x 128 B
#define TILE_B_ELEMS 8192
#define BUF_BYTES (2*TILE_A_BYTES + 2*TILE_B_BYTES)   // 49152
#define DYN_SMEM (2*BUF_BYTES)                         // 98304 (2 CTAs/SM)

// ---------------- device scratch ----------------
__device__ float g_c[BEFF * HID];
__device__ float g_hF[BEFF * HID];
__device__ float g_hy[BEFF * HID];
__device__ float g_base[BEFF * GATES];
__device__ float g_m2[BEFF * MDIM];
__device__ float g_encb[GATES];
__device__ __align__(256) __nv_bfloat16 g_hbf[2][2][BEFF * HID];
__device__ __align__(256) __nv_bfloat16 g_m1bf[2][BEFF * MDIM];
__device__ __align__(256) __nv_bfloat16 g_xbf[2][WSTEPS * BEFF * 64];
__device__ __align__(256) __nv_bfloat16 g_ybf[2][(WSTEPS + 1) * BEFF * 64]; // slot WSTEPS stays 0
__device__ __align__(256) __nv_bfloat16 g_Benc[2][16 * 9 * TILE_B_ELEMS];
__device__ __align__(256) __nv_bfloat16 g_Bdec[2][16 * 9 * TILE_B_ELEMS];
__device__ __align__(256) __nv_bfloat16 g_Bm1[2][4 * 8 * TILE_B_ELEMS];
__device__ __align__(256) __nv_bfloat16 g_Bm2[2][4 * 8 * TILE_B_ELEMS];

// ---------------- helpers ----------------
__device__ __forceinline__ float sigf(float x) { return 1.0f / (1.0f + __expf(-x)); }
__device__ __forceinline__ uint32_t s2u(const void* p) {
    return (uint32_t)__cvta_generic_to_shared(p);
}
__device__ __forceinline__ void cpa4(uint32_t d, const void* s) {
    asm volatile("cp.async.ca.shared.global [%0], [%1], 4;" :: "r"(d), "l"(s));
}
__device__ __forceinline__ void cpa4p(uint32_t d, const void* s, int sz) {
    asm volatile("cp.async.ca.shared.global [%0], [%1], 4, %2;" :: "r"(d), "l"(s), "r"(sz));
}
__device__ __forceinline__ void cpa16(uint32_t d, const void* s) {
    asm volatile("cp.async.cg.shared.global [%0], [%1], 16;" :: "r"(d), "l"(s));
}
__device__ __forceinline__ void cp_commit() { asm volatile("cp.async.commit_group;"); }
__device__ __forceinline__ void cp_wait0()  { asm volatile("cp.async.wait_group 0;"); }
__device__ __forceinline__ void cp_wait1()  { asm volatile("cp.async.wait_group 1;"); }

#define SWZ(o) ((o) ^ (((o) >> 3) & 0x70))

#define LDM_X4(r, a) \
    asm volatile("ldmatrix.sync.aligned.m8n8.x4.shared.b16 {%0,%1,%2,%3}, [%4];" \
        : "=r"((r)[0]), "=r"((r)[1]), "=r"((r)[2]), "=r"((r)[3]) : "r"(a))

#define MMA16816(d, a, b) \
    asm volatile("mma.sync.aligned.m16n8k16.row.col.f32.bf16.bf16.f32 " \
        "{%0,%1,%2,%3}, {%4,%5,%6,%7}, {%8,%9}, {%0,%1,%2,%3};" \
        : "+f"((d)[0]), "+f"((d)[1]), "+f"((d)[2]), "+f"((d)[3]) \
        : "r"((a)[0]), "r"((a)[1]), "r"((a)[2]), "r"((a)[3]), "r"((b)[0]), "r"((b)[1]))

// ---------------- fused init kernels --------------------------------------
// Build pre-swizzled bf16 hi/lo B tiles: blocks of 128 rows x 64 k (16 KB).
// gateBlocked: tile row r -> weight row (r>>5)*HID + bn*32 + (r&31)  (4 gates x 32 j)
// else:        weight row bn*128 + r
__device__ __forceinline__ void conv_unit(int u, const float* W, int ldw, int Kmain,
                                          int gateBlocked, const float* Wx, int ldx, int Kx,
                                          int nCh,
                                          __nv_bfloat16* outHi, __nv_bfloat16* outLo) {
    int bn = u / (nCh * 1024);
    int rem = u - bn * nCh * 1024;
    int c = rem / 1024;
    int unit = rem & 1023;
    int r = unit >> 3, c16 = unit & 7;
    int srow = gateBlocked ? ((r >> 5) * HID + bn * 32 + (r & 31)) : (bn * 128 + r);
    bool xc = (Wx != nullptr) && (c == nCh - 1);
    unsigned short hb[8], lb[8];
#pragma unroll
    for (int e = 0; e < 8; e++) {
        int k = c16 * 8 + e;
        float v;
        if (xc) v = (k < Kx) ? Wx[(size_t)srow * ldx + k] : 0.0f;
        else {
            int kk = c * 64 + k;
            v = (kk < Kmain) ? W[(size_t)srow * ldw + kk] : 0.0f;
        }
        __nv_bfloat16 h = __float2bfloat16(v);
        hb[e] = __bfloat16_as_ushort(h);
        lb[e] = __bfloat16_as_ushort(__float2bfloat16(v - __bfloat162float(h)));
    }
    uint32_t so = SWZ((uint32_t)(r * 128 + c16 * 16));
    size_t dstu = (size_t)(bn * nCh + c) * 1024 + (so >> 4);
    uint4 vh, vl;
    vh.x = hb[0] | (hb[1] << 16); vh.y = hb[2] | (hb[3] << 16);
    vh.z = hb[4] | (hb[5] << 16); vh.w = hb[6] | (hb[7] << 16);
    vl.x = lb[0] | (lb[1] << 16); vl.y = lb[2] | (lb[3] << 16);
    vl.z = lb[4] | (lb[5] << 16); vl.w = lb[6] | (lb[7] << 16);
    ((uint4*)outHi)[dstu] = vh;
    ((uint4*)outLo)[dstu] = vl;
}

__global__ void convAll_kernel(const float* eWhh, const float* eWih,
                               const float* dWhh, const float* dWih512,
                               const float* m1W, const float* m2W,
                               __nv_bfloat16* Benc, __nv_bfloat16* BencL,
                               __nv_bfloat16* Bdec, __nv_bfloat16* BdecL,
                               __nv_bfloat16* Bm1, __nv_bfloat16* Bm1L,
                               __nv_bfloat16* Bm2, __nv_bfloat16* Bm2L) {
    const int ENC_U = 16 * 9 * 1024;  // 147456
    const int MLP_U = 4 * 8 * 1024;   // 32768
    const int total = 2 * ENC_U + 2 * MLP_U;
    for (int u = blockIdx.x * blockDim.x + threadIdx.x; u < total;
         u += gridDim.x * blockDim.x) {
        if (u < ENC_U)
            conv_unit(u, eWhh, 512, 512, 1, eWih, 25, 25, 9, Benc, BencL);
        else if (u < 2 * ENC_U)
            conv_unit(u - ENC_U, dWhh, 512, 512, 1, dWih512, 537, 25, 9, Bdec, BdecL);
        else if (u < 2 * ENC_U + MLP_U)
            conv_unit(u - 2 * ENC_U, m1W, 512, 512, 0, nullptr, 0, 0, 8, Bm1, Bm1L);
        else
            conv_unit(u - 2 * ENC_U - MLP_U, m2W, 512, 512, 0, nullptr, 0, 0, 8, Bm2, Bm2L);
    }
}

// zeros (c, h-hi, h-lo) + x conversion + enc bias add, one launch
__global__ void prep_kernel(const float* __restrict__ em,
                            __nv_bfloat16* __restrict__ xhi, __nv_bfloat16* __restrict__ xlo,
                            const float* __restrict__ b1, const float* __restrict__ b2,
                            float* __restrict__ encb,
                            uint4* __restrict__ zc, uint4* __restrict__ zh0,
                            uint4* __restrict__ zh1) {
    const int NZC = BEFF * HID / 4;
    const int NZH = BEFF * HID / 8;
    const int NCX = WSTEPS * BEFF * 64;
    const int total = NZC + 2 * NZH + NCX + GATES;
    uint4 z = {0, 0, 0, 0};
    for (int u = blockIdx.x * blockDim.x + threadIdx.x; u < total;
         u += gridDim.x * blockDim.x) {
        if (u < NZC) { zc[u] = z; }
        else if (u < NZC + NZH) { zh0[u - NZC] = z; }
        else if (u < NZC + 2 * NZH) { zh1[u - NZC - NZH] = z; }
        else if (u < NZC + 2 * NZH + NCX) {
            int idx = u - (NZC + 2 * NZH);
            int t = idx / (BEFF * 64);
            int rem = idx - t * BEFF * 64;
            int i = rem >> 6, k = rem & 63;
            float v = (k < FEAT) ? em[(size_t)i * 1250 + t * FEAT + k] : 0.0f;
            __nv_bfloat16 h = __float2bfloat16(v);
            xhi[idx] = h;
            xlo[idx] = __float2bfloat16(v - __bfloat162float(h));
        } else {
            int i = u - (NZC + 2 * NZH + NCX);
            encb[i] = b1[i] + b2[i];
        }
    }
}

__global__ void zero3_kernel(uint4* __restrict__ zc, uint4* __restrict__ zh0,
                             uint4* __restrict__ zh1) {
    const int NZC = BEFF * HID / 4;
    const int NZH = BEFF * HID / 8;
    const int total = NZC + 2 * NZH;
    uint4 z = {0, 0, 0, 0};
    for (int u = blockIdx.x * blockDim.x + threadIdx.x; u < total;
         u += gridDim.x * blockDim.x) {
        if (u < NZC) zc[u] = z;
        else if (u < NZC + NZH) zh0[u - NZC] = z;
        else zh1[u - NZC - NZH] = z;
    }
}

// ---------------- SIMT GEMM (small shapes) ----------------
template <int ACT>
__global__ void __launch_bounds__(256, 2)
gemm_kernel(const float* __restrict__ A, int lda,
            const float* __restrict__ W, int ldw,
            const float* __restrict__ b1, const float* __restrict__ b2,
            float* __restrict__ C, int ldc, int N, int K) {
    __shared__ __align__(16) float As[2][16][68];
    __shared__ __align__(16) float Bs[2][16][68];
    const int tid = threadIdx.x;
    const int tx = tid & 15, ty = tid >> 4;
    const int n0 = blockIdx.x * 64, m0 = blockIdx.y * 64;
    const int lk = tid & 15, lr = tid >> 4;
    float acc[4][4] = {};
    const int nch = K >> 4;
    auto issue = [&](int k0, int b) {
#pragma unroll
        for (int i = 0; i < 4; i++) {
            const int row = lr + 16 * i;
            cpa4(s2u(&As[b][lk][row]), &A[(size_t)(n0 + row) * lda + k0 + lk]);
            const int m = m0 + row;
            const int mc = (m < N) ? m : 0;
            cpa4p(s2u(&Bs[b][lk][row]), &W[(size_t)mc * ldw + k0 + lk], (m < N) ? 4 : 0);
        }
        cp_commit();
    };
    issue(0, 0);
    for (int c = 0; c < nch; c++) {
        if (c + 1 < nch) { issue((c + 1) * 16, (c + 1) & 1); cp_wait1(); }
        else             { cp_wait0(); }
        __syncthreads();
        const int p = c & 1;
#pragma unroll
        for (int kk = 0; kk < 16; kk++) {
            float4 a4 = *(const float4*)&As[p][kk][ty * 4];
            float4 b4 = *(const float4*)&Bs[p][kk][tx * 4];
            float av[4] = {a4.x, a4.y, a4.z, a4.w};
            float bv[4] = {b4.x, b4.y, b4.z, b4.w};
#pragma unroll
            for (int r = 0; r < 4; r++)
#pragma unroll
                for (int c2 = 0; c2 < 4; c2++)
                    acc[r][c2] += av[r] * bv[c2];
        }
        __syncthreads();
    }
#pragma unroll
    for (int r = 0; r < 4; r++) {
        const int n = n0 + ty * 4 + r;
#pragma unroll
        for (int c2 = 0; c2 < 4; c2++) {
            const int m = m0 + tx * 4 + c2;
            if (m < N) {
                float v = acc[r][c2];
                if (b1) v += b1[m];
                if (b2) v += b2[m];
                if (ACT == 1) v = tanhf(v);
                C[(size_t)n * ldc + m] = v;
            }
        }
    }
}

// out projection (N=25) + bf16 hi/lo y emit for decoder recurrence
__global__ void __launch_bounds__(256, 2)
outproj_kernel(const float* __restrict__ A, const float* __restrict__ W,
               const float* __restrict__ b, float* __restrict__ pred,
               __nv_bfloat16* __restrict__ yhi, __nv_bfloat16* __restrict__ ylo) {
    __shared__ __align__(16) float As[2][16][68];
    __shared__ __align__(16) float Bs[2][16][68];
    const int tid = threadIdx.x;
    const int tx = tid & 15, ty = tid >> 4;
    const int n0 = blockIdx.x * 64;
    const int lk = tid & 15, lr = tid >> 4;
    float acc[4][4] = {};
    auto issue = [&](int k0, int bb) {
#pragma unroll
        for (int i = 0; i < 4; i++) {
            const int row = lr + 16 * i;
            cpa4(s2u(&As[bb][lk][row]), &A[(size_t)(n0 + row) * MDIM + k0 + lk]);
            const int mc = (row < FEAT) ? row : 0;
            cpa4p(s2u(&Bs[bb][lk][row]), &W[(size_t)mc * MDIM + k0 + lk], (row < FEAT) ? 4 : 0);
        }
        cp_commit();
    };
    issue(0, 0);
    for (int c = 0; c < 32; c++) {
        if (c + 1 < 32) { issue((c + 1) * 16, (c + 1) & 1); cp_wait1(); }
        else            { cp_wait0(); }
        __syncthreads();
        const int p = c & 1;
#pragma unroll
        for (int kk = 0; kk < 16; kk++) {
            float4 a4 = *(const float4*)&As[p][kk][ty * 4];
            float4 b4 = *(const float4*)&Bs[p][kk][tx * 4];
            float av[4] = {a4.x, a4.y, a4.z, a4.w};
            float bv[4] = {b4.x, b4.y, b4.z, b4.w};
#pragma unroll
            for (int r = 0; r < 4; r++)
#pragma unroll
                for (int c2 = 0; c2 < 4; c2++)
                    acc[r][c2] += av[r] * bv[c2];
        }
        __syncthreads();
    }
#pragma unroll
    for (int r = 0; r < 4; r++) {
        const int n = n0 + ty * 4 + r;
#pragma unroll
        for (int c2 = 0; c2 < 4; c2++) {
            const int m = tx * 4 + c2;
            if (m < FEAT) {
                float v = acc[r][c2] + b[m];
                pred[(size_t)n * 1250 + m] = v;
                __nv_bfloat16 h = __float2bfloat16(v);
                yhi[(size_t)n * 64 + m] = h;
                ylo[(size_t)n * 64 + m] = __float2bfloat16(v - __bfloat162float(h));
            }
        }
    }
}

// ---------------- mma.sync GEMM (bf16 3-term split), TM=64 x TN=128 ----------
// 256 threads = 8 warps (2 M x 4 N), warp tile 32x32, acc 32 regs -> 2 CTAs/SM.
// EPI: 0 = LSTM cell (TN = 4 gates x 32 j, j0 = bn*32), 1 = tanh->bf16, 2 = tanh->fp32
template <int NCH, int HASX, int EPI>
__global__ void __launch_bounds__(256, 2)
mma_kernel(const __nv_bfloat16* __restrict__ ahi, const __nv_bfloat16* __restrict__ alo,
           const __nv_bfloat16* __restrict__ xhi, const __nv_bfloat16* __restrict__ xlo,
           const __nv_bfloat16* __restrict__ Bth, const __nv_bfloat16* __restrict__ Btl,
           const float* __restrict__ base, int base_stride,
           const float* __restrict__ bias,
           float* __restrict__ c_io, float* __restrict__ hF,
           __nv_bfloat16* __restrict__ ohi, __nv_bfloat16* __restrict__ olo,
           float* __restrict__ outF) {
    extern __shared__ __align__(1024) char smem[];
    const int tid = threadIdx.x;
    const int wid = tid >> 5;
    const int lane = tid & 31;
    const int n0 = blockIdx.x * 64;
    const int bn = blockIdx.y;
    const int wm = wid & 1;        // M block (32 rows)
    const int wn = wid >> 1;       // N block (32 cols)
    const int ldAmain = (NCH - HASX) * 128;   // bytes per A row

    float acc[2][4][4] = {};       // [mi][pr*2+t2][frag]

    auto do_copy = [&](int c, int p) {
        char* bb = smem + p * BUF_BYTES;
        uint32_t sAh = s2u(bb), sAl = sAh + TILE_A_BYTES;
        uint32_t sBh = sAh + 2 * TILE_A_BYTES, sBl = sBh + TILE_B_BYTES;
        const char *ap, *alp; int ld;
        if (HASX && c == NCH - 1) { ap = (const char*)xhi; alp = (const char*)xlo; ld = 128; }
        else { ap = (const char*)ahi + c * 128; alp = (const char*)alo + c * 128; ld = ldAmain; }
#pragma unroll
        for (int i = 0; i < 2; i++) {
            int u = tid + i * 256;         // 512 units of 16B for 64x128B tile
            int r = u >> 3, c16 = u & 7;
            uint32_t so = SWZ((uint32_t)(r * 128 + c16 * 16));
            cpa16(sAh + so, ap + (size_t)(n0 + r) * ld + c16 * 16);
            cpa16(sAl + so, alp + (size_t)(n0 + r) * ld + c16 * 16);
        }
        const char* bh = (const char*)Bth + (size_t)(bn * NCH + c) * TILE_B_BYTES;
        const char* bl = (const char*)Btl + (size_t)(bn * NCH + c) * TILE_B_BYTES;
#pragma unroll
        for (int i = 0; i < 4; i++) {
            int u = tid + i * 256;         // 1024 units for 128x128B tile
            cpa16(sBh + u * 16, bh + (size_t)u * 16);
            cpa16(sBl + u * 16, bl + (size_t)u * 16);
        }
        cp_commit();
    };

    do_copy(0, 0);
    if (NCH > 1) do_copy(1, 1);
    for (int c = 0; c < NCH; c++) {
        const int p = c & 1;
        if (c + 1 < NCH) cp_wait1(); else cp_wait0();
        __syncthreads();
        uint32_t baseu = s2u(smem + p * BUF_BYTES);
        uint32_t aHb = baseu, aLb = baseu + TILE_A_BYTES;
        uint32_t bHb = baseu + 2 * TILE_A_BYTES, bLb = bHb + TILE_B_BYTES;
#pragma unroll
        for (int ks = 0; ks < 4; ks++) {
            uint32_t ah[2][4], al[2][4];
#pragma unroll
            for (int mi = 0; mi < 2; mi++) {
                int rowA = wm * 32 + mi * 16 + (lane & 15);
                uint32_t off = SWZ((uint32_t)(rowA * 128 + ks * 32 + (lane >> 4) * 16));
                LDM_X4(ah[mi], aHb + off);
                LDM_X4(al[mi], aLb + off);
            }
#pragma unroll
            for (int pr = 0; pr < 2; pr++) {
                int rowB = wn * 32 + pr * 16 + ((lane >> 4) << 3) + (lane & 7);
                uint32_t offB = SWZ((uint32_t)(rowB * 128 + ks * 32 + ((lane >> 3) & 1) * 16));
                uint32_t bh[4], bl[4];
                LDM_X4(bh, bHb + offB);
                LDM_X4(bl, bLb + offB);
#pragma unroll
                for (int mi = 0; mi < 2; mi++) {
#pragma unroll
                    for (int t2 = 0; t2 < 2; t2++) {
                        float* d = acc[mi][pr * 2 + t2];
                        MMA16816(d, ah[mi], bh + t2 * 2);
                        MMA16816(d, ah[mi], bl + t2 * 2);
                        MMA16816(d, al[mi], bh + t2 * 2);
                    }
                }
            }
        }
        __syncthreads();
        if (c + 2 < NCH) do_copy(c + 2, p);
    }

    // stage accumulators to smem: sAcc[64][128] fp32 (32 KB)
    float* sAcc = (float*)smem;
#pragma unroll
    for (int mi = 0; mi < 2; mi++) {
#pragma unroll
        for (int ni = 0; ni < 4; ni++) {
            int row = wm * 32 + mi * 16 + (lane >> 2);
            int col = wn * 32 + ni * 8 + 2 * (lane & 3);
            *(float2*)&sAcc[row * 128 + col] = make_float2(acc[mi][ni][0], acc[mi][ni][1]);
            *(float2*)&sAcc[(row + 8) * 128 + col] = make_float2(acc[mi][ni][2], acc[mi][ni][3]);
        }
    }
    __syncthreads();

    if (EPI == 0) {
        const int jcol = tid & 31;
        const int rowgrp = tid >> 5;     // 0..7
        const int j = bn * 32 + jcol;
#pragma unroll
        for (int rr = 0; rr < 8; rr++) {
            int row = rr * 8 + rowgrp;
            int n = n0 + row;
            const float* bp = base + (size_t)n * base_stride;
            float iv = sAcc[row * 128 + jcol]      + bp[j];
            float fv = sAcc[row * 128 + 32 + jcol] + bp[512 + j];
            float gv = sAcc[row * 128 + 64 + jcol] + bp[1024 + j];
            float ov = sAcc[row * 128 + 96 + jcol] + bp[1536 + j];
            float cold = c_io[(size_t)n * HID + j];
            float cn = sigf(fv) * cold + sigf(iv) * tanhf(gv);
            float hn = sigf(ov) * tanhf(cn);
            c_io[(size_t)n * HID + j] = cn;
            hF[(size_t)n * HID + j] = hn;
            __nv_bfloat16 h = __float2bfloat16(hn);
            ohi[(size_t)n * HID + j] = h;
            olo[(size_t)n * HID + j] = __float2bfloat16(hn - __bfloat162float(h));
        }
    } else {
        const int col = tid & 127;
        const int rowgrp = tid >> 7;     // 0..1
        const int gcol = bn * 128 + col;
#pragma unroll
        for (int rr = 0; rr < 32; rr++) {
            int row = rr * 2 + rowgrp;
            int n = n0 + row;
            float v = tanhf(sAcc[row * 128 + col] + bias[gcol]);
            if (EPI == 2) {
                outF[(size_t)n * MDIM + gcol] = v;
            } else {
                __nv_bfloat16 h = __float2bfloat16(v);
                ohi[(size_t)n * MDIM + gcol] = h;
                olo[(size_t)n * MDIM + gcol] = __float2bfloat16(v - __bfloat162float(h));
            }
        }
    }
}

// ---------------- fused 3DMM head ----------------
__global__ void __launch_bounds__(256)
head3dmm_kernel(const float* __restrict__ pred,
                const float* __restrict__ C1, const float* __restrict__ b1,
                const float* __restrict__ C2, const float* __restrict__ b2,
                float* __restrict__ coeff) {
    __shared__ __align__(16) float sP[64][FEAT + 1];
    __shared__ __align__(16) float sC1c[64][FEAT + 1];
    __shared__ __align__(16) float sHid[64][64];
    const int tid = threadIdx.x;
    const int r0 = blockIdx.x * 64;
    for (int i = tid; i < 64 * FEAT; i += 256)
        sP[i / FEAT][i % FEAT] = pred[(size_t)(r0 + i / FEAT) * FEAT + i % FEAT];
    const int row = tid >> 2;
    const int l4 = tid & 3;
    float acc[15];
#pragma unroll
    for (int q = 0; q < 15; q++) acc[q] = 0.0f;
    for (int jc = 0; jc < HID; jc += 64) {
        __syncthreads();
        for (int i = tid; i < 64 * FEAT; i += 256)
            sC1c[i / FEAT][i % FEAT] = C1[(size_t)(jc + i / FEAT) * FEAT + i % FEAT];
        __syncthreads();
#pragma unroll
        for (int jj = 0; jj < 16; jj++) {
            const int jl = l4 * 16 + jj;
            float v = b1[jc + jl];
#pragma unroll
            for (int k = 0; k < FEAT; k++)
                v += sP[row][k] * sC1c[jl][k];
            sHid[row][jl] = tanhf(v);
        }
        __syncthreads();
        for (int q = 0; q < 15; q++) {
            const int m = l4 + q * 4;
            if (m < NC3D) {
                float s = 0.0f;
                const float* c2r = C2 + (size_t)m * HID + jc;
#pragma unroll
                for (int jj = 0; jj < 64; jj++)
                    s += sHid[row][jj] * c2r[jj];
                acc[q] += s;
            }
        }
    }
#pragma unroll
    for (int q = 0; q < 15; q++) {
        const int m = l4 + q * 4;
        if (m < NC3D)
            coeff[(size_t)(r0 + row) * NC3D + m] = acc[q] + b2[m];
    }
}

// ---------------- host orchestration ----------------
extern "C" void kernel_launch(void* const* d_in, const int* in_sizes, int n_in,
                              void* d_out, int out_size) {
    const float* em   = (const float*)d_in[0];
    const float* eWih = (const float*)d_in[2];
    const float* eWhh = (const float*)d_in[3];
    const float* ebih = (const float*)d_in[4];
    const float* ebhh = (const float*)d_in[5];
    const float* muW  = (const float*)d_in[6];
    const float* mub  = (const float*)d_in[7];
    const float* lvW  = (const float*)d_in[8];
    const float* lvb  = (const float*)d_in[9];
    const float* zW   = (const float*)d_in[10];
    const float* zb   = (const float*)d_in[11];
    const float* dWih = (const float*)d_in[12];
    const float* dWhh = (const float*)d_in[13];
    const float* dbih = (const float*)d_in[14];
    const float* dbhh = (const float*)d_in[15];
    const float* m1W  = (const float*)d_in[16];
    const float* m1b  = (const float*)d_in[17];
    const float* m2W  = (const float*)d_in[18];
    const float* m2b  = (const float*)d_in[19];
    const float* oW   = (const float*)d_in[20];
    const float* ob   = (const float*)d_in[21];
    const float* c1W  = (const float*)d_in[22];
    const float* c1b  = (const float*)d_in[23];
    const float* c2W  = (const float*)d_in[24];
    const float* c2b  = (const float*)d_in[25];

    float* out   = (float*)d_out;
    float* pred  = out;
    float* coeff = out + 2400000;
    float* mu    = out + 2400000 + 5568000;
    float* lv    = mu + 491520;

    float *cbuf, *hF, *hy, *base, *m2, *encb;
    __nv_bfloat16 *hbf, *m1bf, *xbf, *ybf, *Benc, *Bdec, *Bm1, *Bm2;
    cudaGetSymbolAddress((void**)&cbuf, g_c);
    cudaGetSymbolAddress((void**)&hF,   g_hF);
    cudaGetSymbolAddress((void**)&hy,   g_hy);
    cudaGetSymbolAddress((void**)&base, g_base);
    cudaGetSymbolAddress((void**)&m2,   g_m2);
    cudaGetSymbolAddress((void**)&encb, g_encb);
    cudaGetSymbolAddress((void**)&hbf,  g_hbf);
    cudaGetSymbolAddress((void**)&m1bf, g_m1bf);
    cudaGetSymbolAddress((void**)&xbf,  g_xbf);
    cudaGetSymbolAddress((void**)&ybf,  g_ybf);
    cudaGetSymbolAddress((void**)&Benc, g_Benc);
    cudaGetSymbolAddress((void**)&Bdec, g_Bdec);
    cudaGetSymbolAddress((void**)&Bm1,  g_Bm1);
    cudaGetSymbolAddress((void**)&Bm2,  g_Bm2);
    const size_t HSZ = (size_t)BEFF * HID;
    const size_t XSL = (size_t)BEFF * 64;
    __nv_bfloat16* hbfp[2][2] = {{hbf, hbf + HSZ}, {hbf + 2 * HSZ, hbf + 3 * HSZ}};
    __nv_bfloat16* BencL = Benc + 16 * 9 * TILE_B_ELEMS;
    __nv_bfloat16* BdecL = Bdec + 16 * 9 * TILE_B_ELEMS;
    __nv_bfloat16* Bm1L = Bm1 + 4 * 8 * TILE_B_ELEMS;
    __nv_bfloat16* Bm2L = Bm2 + 4 * 8 * TILE_B_ELEMS;
    __nv_bfloat16* xlo = xbf + (size_t)WSTEPS * XSL;
    __nv_bfloat16* ylo = ybf + (size_t)(WSTEPS + 1) * XSL;

    cudaFuncSetAttribute(mma_kernel<9,1,0>, cudaFuncAttributeMaxDynamicSharedMemorySize, DYN_SMEM);
    cudaFuncSetAttribute(mma_kernel<8,0,1>, cudaFuncAttributeMaxDynamicSharedMemorySize, DYN_SMEM);
    cudaFuncSetAttribute(mma_kernel<8,0,2>, cudaFuncAttributeMaxDynamicSharedMemorySize, DYN_SMEM);

    const dim3 blk(256);
    // launch 1: all weight conversions
    convAll_kernel<<<1408, blk>>>(eWhh, eWih, dWhh, dWih + 512, m1W, m2W,
                                  Benc, BencL, Bdec, BdecL, Bm1, Bm1L, Bm2, Bm2L);
    // launch 2: zeros + x conversion + enc bias
    prep_kernel<<<2048, blk>>>(em, xbf, xlo, ebih, ebhh, encb,
                               (uint4*)cbuf, (uint4*)hbfp[0][0], (uint4*)hbfp[0][1]);

    // ---- encoder ----
    for (int t = 0; t < WSTEPS; t++) {
        int s = t & 1, d = s ^ 1;
        mma_kernel<9,1,0><<<dim3(30, 16), blk, DYN_SMEM>>>(
            hbfp[s][0], hbfp[s][1], xbf + (size_t)t * XSL, xlo + (size_t)t * XSL,
            Benc, BencL, encb, 0, nullptr, cbuf, hF, hbfp[d][0], hbfp[d][1], nullptr);
    }

    // ---- latent head ----
    gemm_kernel<0><<<dim3(30, 4), blk>>>(hF, HID, muW, HID, mub, nullptr, mu, ZDIM, ZDIM, HID);
    gemm_kernel<0><<<dim3(30, 4), blk>>>(hF, HID, lvW, HID, lvb, nullptr, lv, ZDIM, ZDIM, HID);
    gemm_kernel<0><<<dim3(30, 8), blk>>>(mu, ZDIM, zW, ZDIM, zb, nullptr, hy, HID, HID, ZDIM);
    gemm_kernel<0><<<dim3(30, 32), blk>>>(hy, HID, dWih, HID + FEAT, dbih, dbhh,
                                          base, GATES, GATES, HID);

    // reset state for decoder (1 launch)
    zero3_kernel<<<512, blk>>>((uint4*)cbuf, (uint4*)hbfp[0][0], (uint4*)hbfp[0][1]);

    // ---- decoder ----
    for (int t = 0; t < WSTEPS; t++) {
        int s = t & 1, d = s ^ 1;
        const __nv_bfloat16* yh = (t == 0) ? (ybf + (size_t)WSTEPS * XSL) : (ybf + (size_t)(t - 1) * XSL);
        const __nv_bfloat16* yl = (t == 0) ? (ylo + (size_t)WSTEPS * XSL) : (ylo + (size_t)(t - 1) * XSL);
        mma_kernel<9,1,0><<<dim3(30, 16), blk, DYN_SMEM>>>(
            hbfp[s][0], hbfp[s][1], yh, yl,
            Bdec, BdecL, base, GATES, nullptr, cbuf, hF, hbfp[d][0], hbfp[d][1], nullptr);
        mma_kernel<8,0,1><<<dim3(30, 4), blk, DYN_SMEM>>>(
            hbfp[d][0], hbfp[d][1], nullptr, nullptr,
            Bm1, Bm1L, nullptr, 0, m1b, nullptr, nullptr, m1bf, m1bf + HSZ, nullptr);
        mma_kernel<8,0,2><<<dim3(30, 4), blk, DYN_SMEM>>>(
            m1bf, m1bf + HSZ, nullptr, nullptr,
            Bm2, Bm2L, nullptr, 0, m2b, nullptr, nullptr, nullptr, nullptr, m2);
        outproj_kernel<<<30, blk>>>(m2, oW, ob, pred + t * FEAT,
                                    ybf + (size_t)t * XSL, ylo + (size_t)t * XSL);
    }

    // ---- 3DMM head ----
    head3dmm_kernel<<<1500, blk>>>(pred, c1W, c1b, c2W, c2b, coeff);
}

// round 14
// speedup vs baseline: 1.9450x; 1.0059x over previous
#include <cuda_runtime.h>
#include <cuda_bf16.h>
#include <math.h>
#include <stdint.h>

#define BEFF   1920
#define HID    512
#define FEAT   25
#define ZDIM   256
#define MDIM   512
#define NC3D   58
#define WSTEPS 50
#define GATES  2048

// tile config: TM=64 rows x TN=128 cols, chunks of K=64
#define TILE_A_BYTES 8192               // 64 rows x 128 B
#define TILE_B_BYTES 16384              // 128 rows x 128 B
#define TILE_B_ELEMS 8192
#define BUF_BYTES (2*TILE_A_BYTES + 2*TILE_B_BYTES)   // 49152
#define DYN_SMEM (2*BUF_BYTES)                         // 98304 (2 CTAs/SM)

// ---------------- device scratch ----------------
__device__ float g_c[BEFF * HID];
__device__ float g_hF[BEFF * HID];
__device__ float g_hy[BEFF * HID];
__device__ float g_base[BEFF * GATES];
__device__ float g_m2[BEFF * MDIM];
__device__ float g_encb[GATES];
__device__ __align__(256) __nv_bfloat16 g_hbf[2][2][BEFF * HID];
__device__ __align__(256) __nv_bfloat16 g_m1bf[2][BEFF * MDIM];
__device__ __align__(256) __nv_bfloat16 g_xbf[2][WSTEPS * BEFF * 64];
__device__ __align__(256) __nv_bfloat16 g_ybf[2][(WSTEPS + 1) * BEFF * 64]; // slot WSTEPS stays 0
__device__ __align__(256) __nv_bfloat16 g_Benc[2][16 * 9 * TILE_B_ELEMS];
__device__ __align__(256) __nv_bfloat16 g_Bdec[2][16 * 9 * TILE_B_ELEMS];
__device__ __align__(256) __nv_bfloat16 g_Bm1[2][4 * 8 * TILE_B_ELEMS];
__device__ __align__(256) __nv_bfloat16 g_Bm2[2][4 * 8 * TILE_B_ELEMS];

// ---------------- helpers ----------------
__device__ __forceinline__ float sigf(float x) { return 1.0f / (1.0f + __expf(-x)); }
__device__ __forceinline__ uint32_t s2u(const void* p) {
    return (uint32_t)__cvta_generic_to_shared(p);
}
__device__ __forceinline__ void cpa4(uint32_t d, const void* s) {
    asm volatile("cp.async.ca.shared.global [%0], [%1], 4;" :: "r"(d), "l"(s));
}
__device__ __forceinline__ void cpa4p(uint32_t d, const void* s, int sz) {
    asm volatile("cp.async.ca.shared.global [%0], [%1], 4, %2;" :: "r"(d), "l"(s), "r"(sz));
}
__device__ __forceinline__ void cpa16(uint32_t d, const void* s) {
    asm volatile("cp.async.cg.shared.global [%0], [%1], 16;" :: "r"(d), "l"(s));
}
__device__ __forceinline__ void cp_commit() { asm volatile("cp.async.commit_group;"); }
__device__ __forceinline__ void cp_wait0()  { asm volatile("cp.async.wait_group 0;"); }
__device__ __forceinline__ void cp_wait1()  { asm volatile("cp.async.wait_group 1;"); }

#define SWZ(o) ((o) ^ (((o) >> 3) & 0x70))

#define LDM_X4(r, a) \
    asm volatile("ldmatrix.sync.aligned.m8n8.x4.shared.b16 {%0,%1,%2,%3}, [%4];" \
        : "=r"((r)[0]), "=r"((r)[1]), "=r"((r)[2]), "=r"((r)[3]) : "r"(a))

#define MMA16816(d, a, b) \
    asm volatile("mma.sync.aligned.m16n8k16.row.col.f32.bf16.bf16.f32 " \
        "{%0,%1,%2,%3}, {%4,%5,%6,%7}, {%8,%9}, {%0,%1,%2,%3};" \
        : "+f"((d)[0]), "+f"((d)[1]), "+f"((d)[2]), "+f"((d)[3]) \
        : "r"((a)[0]), "r"((a)[1]), "r"((a)[2]), "r"((a)[3]), "r"((b)[0]), "r"((b)[1]))

// ---------------- fused init kernels --------------------------------------
// Build pre-swizzled bf16 hi/lo B tiles: blocks of 128 rows x 64 k (16 KB).
// gateBlocked: tile row r -> weight row (r>>5)*HID + bn*32 + (r&31)
__device__ __forceinline__ void conv_unit(int u, const float* W, int ldw, int Kmain,
                                          int gateBlocked, const float* Wx, int ldx, int Kx,
                                          int nCh,
                                          __nv_bfloat16* outHi, __nv_bfloat16* outLo) {
    int bn = u / (nCh * 1024);
    int rem = u - bn * nCh * 1024;
    int c = rem / 1024;
    int unit = rem & 1023;
    int r = unit >> 3, c16 = unit & 7;
    int srow = gateBlocked ? ((r >> 5) * HID + bn * 32 + (r & 31)) : (bn * 128 + r);
    bool xc = (Wx != nullptr) && (c == nCh - 1);
    unsigned short hb[8], lb[8];
#pragma unroll
    for (int e = 0; e < 8; e++) {
        int k = c16 * 8 + e;
        float v;
        if (xc) v = (k < Kx) ? Wx[(size_t)srow * ldx + k] : 0.0f;
        else {
            int kk = c * 64 + k;
            v = (kk < Kmain) ? W[(size_t)srow * ldw + kk] : 0.0f;
        }
        __nv_bfloat16 h = __float2bfloat16(v);
        hb[e] = __bfloat16_as_ushort(h);
        lb[e] = __bfloat16_as_ushort(__float2bfloat16(v - __bfloat162float(h)));
    }
    uint32_t so = SWZ((uint32_t)(r * 128 + c16 * 16));
    size_t dstu = (size_t)(bn * nCh + c) * 1024 + (so >> 4);
    uint4 vh, vl;
    vh.x = hb[0] | (hb[1] << 16); vh.y = hb[2] | (hb[3] << 16);
    vh.z = hb[4] | (hb[5] << 16); vh.w = hb[6] | (hb[7] << 16);
    vl.x = lb[0] | (lb[1] << 16); vl.y = lb[2] | (lb[3] << 16);
    vl.z = lb[4] | (lb[5] << 16); vl.w = lb[6] | (lb[7] << 16);
    ((uint4*)outHi)[dstu] = vh;
    ((uint4*)outLo)[dstu] = vl;
}

__global__ void convAll_kernel(const float* eWhh, const float* eWih,
                               const float* dWhh, const float* dWih512,
                               const float* m1W, const float* m2W,
                               __nv_bfloat16* Benc, __nv_bfloat16* BencL,
                               __nv_bfloat16* Bdec, __nv_bfloat16* BdecL,
                               __nv_bfloat16* Bm1, __nv_bfloat16* Bm1L,
                               __nv_bfloat16* Bm2, __nv_bfloat16* Bm2L) {
    const int ENC_U = 16 * 9 * 1024;  // 147456
    const int MLP_U = 4 * 8 * 1024;   // 32768
    const int total = 2 * ENC_U + 2 * MLP_U;
    for (int u = blockIdx.x * blockDim.x + threadIdx.x; u < total;
         u += gridDim.x * blockDim.x) {
        if (u < ENC_U)
            conv_unit(u, eWhh, 512, 512, 1, eWih, 25, 25, 9, Benc, BencL);
        else if (u < 2 * ENC_U)
            conv_unit(u - ENC_U, dWhh, 512, 512, 1, dWih512, 537, 25, 9, Bdec, BdecL);
        else if (u < 2 * ENC_U + MLP_U)
            conv_unit(u - 2 * ENC_U, m1W, 512, 512, 0, nullptr, 0, 0, 8, Bm1, Bm1L);
        else
            conv_unit(u - 2 * ENC_U - MLP_U, m2W, 512, 512, 0, nullptr, 0, 0, 8, Bm2, Bm2L);
    }
}

// zeros (c, h-hi, h-lo) + x conversion + enc bias add, one launch
__global__ void prep_kernel(const float* __restrict__ em,
                            __nv_bfloat16* __restrict__ xhi, __nv_bfloat16* __restrict__ xlo,
                            const float* __restrict__ b1, const float* __restrict__ b2,
                            float* __restrict__ encb,
                            uint4* __restrict__ zc, uint4* __restrict__ zh0,
                            uint4* __restrict__ zh1) {
    const int NZC = BEFF * HID / 4;
    const int NZH = BEFF * HID / 8;
    const int NCX = WSTEPS * BEFF * 64;
    const int total = NZC + 2 * NZH + NCX + GATES;
    uint4 z = {0, 0, 0, 0};
    for (int u = blockIdx.x * blockDim.x + threadIdx.x; u < total;
         u += gridDim.x * blockDim.x) {
        if (u < NZC) { zc[u] = z; }
        else if (u < NZC + NZH) { zh0[u - NZC] = z; }
        else if (u < NZC + 2 * NZH) { zh1[u - NZC - NZH] = z; }
        else if (u < NZC + 2 * NZH + NCX) {
            int idx = u - (NZC + 2 * NZH);
            int t = idx / (BEFF * 64);
            int rem = idx - t * BEFF * 64;
            int i = rem >> 6, k = rem & 63;
            float v = (k < FEAT) ? em[(size_t)i * 1250 + t * FEAT + k] : 0.0f;
            __nv_bfloat16 h = __float2bfloat16(v);
            xhi[idx] = h;
            xlo[idx] = __float2bfloat16(v - __bfloat162float(h));
        } else {
            int i = u - (NZC + 2 * NZH + NCX);
            encb[i] = b1[i] + b2[i];
        }
    }
}

__global__ void zero3_kernel(uint4* __restrict__ zc, uint4* __restrict__ zh0,
                             uint4* __restrict__ zh1) {
    const int NZC = BEFF * HID / 4;
    const int NZH = BEFF * HID / 8;
    const int total = NZC + 2 * NZH;
    uint4 z = {0, 0, 0, 0};
    for (int u = blockIdx.x * blockDim.x + threadIdx.x; u < total;
         u += gridDim.x * blockDim.x) {
        if (u < NZC) zc[u] = z;
        else if (u < NZC + NZH) zh0[u - NZC] = z;
        else zh1[u - NZC - NZH] = z;
    }
}

// ---------------- SIMT GEMM (small shapes) ----------------
template <int ACT>
__global__ void __launch_bounds__(256, 2)
gemm_kernel(const float* __restrict__ A, int lda,
            const float* __restrict__ W, int ldw,
            const float* __restrict__ b1, const float* __restrict__ b2,
            float* __restrict__ C, int ldc, int N, int K) {
    __shared__ __align__(16) float As[2][16][68];
    __shared__ __align__(16) float Bs[2][16][68];
    const int tid = threadIdx.x;
    const int tx = tid & 15, ty = tid >> 4;
    const int n0 = blockIdx.x * 64, m0 = blockIdx.y * 64;
    const int lk = tid & 15, lr = tid >> 4;
    float acc[4][4] = {};
    const int nch = K >> 4;
    auto issue = [&](int k0, int b) {
#pragma unroll
        for (int i = 0; i < 4; i++) {
            const int row = lr + 16 * i;
            cpa4(s2u(&As[b][lk][row]), &A[(size_t)(n0 + row) * lda + k0 + lk]);
            const int m = m0 + row;
            const int mc = (m < N) ? m : 0;
            cpa4p(s2u(&Bs[b][lk][row]), &W[(size_t)mc * ldw + k0 + lk], (m < N) ? 4 : 0);
        }
        cp_commit();
    };
    issue(0, 0);
    for (int c = 0; c < nch; c++) {
        if (c + 1 < nch) { issue((c + 1) * 16, (c + 1) & 1); cp_wait1(); }
        else             { cp_wait0(); }
        __syncthreads();
        const int p = c & 1;
#pragma unroll
        for (int kk = 0; kk < 16; kk++) {
            float4 a4 = *(const float4*)&As[p][kk][ty * 4];
            float4 b4 = *(const float4*)&Bs[p][kk][tx * 4];
            float av[4] = {a4.x, a4.y, a4.z, a4.w};
            float bv[4] = {b4.x, b4.y, b4.z, b4.w};
#pragma unroll
            for (int r = 0; r < 4; r++)
#pragma unroll
                for (int c2 = 0; c2 < 4; c2++)
                    acc[r][c2] += av[r] * bv[c2];
        }
        __syncthreads();
    }
#pragma unroll
    for (int r = 0; r < 4; r++) {
        const int n = n0 + ty * 4 + r;
#pragma unroll
        for (int c2 = 0; c2 < 4; c2++) {
            const int m = m0 + tx * 4 + c2;
            if (m < N) {
                float v = acc[r][c2];
                if (b1) v += b1[m];
                if (b2) v += b2[m];
                if (ACT == 1) v = tanhf(v);
                C[(size_t)n * ldc + m] = v;
            }
        }
    }
}

// out projection (N=25) + bf16 hi/lo y emit for decoder recurrence
__global__ void __launch_bounds__(256, 2)
outproj_kernel(const float* __restrict__ A, const float* __restrict__ W,
               const float* __restrict__ b, float* __restrict__ pred,
               __nv_bfloat16* __restrict__ yhi, __nv_bfloat16* __restrict__ ylo) {
    __shared__ __align__(16) float As[2][16][68];
    __shared__ __align__(16) float Bs[2][16][68];
    const int tid = threadIdx.x;
    const int tx = tid & 15, ty = tid >> 4;
    const int n0 = blockIdx.x * 64;
    const int lk = tid & 15, lr = tid >> 4;
    float acc[4][4] = {};
    auto issue = [&](int k0, int bb) {
#pragma unroll
        for (int i = 0; i < 4; i++) {
            const int row = lr + 16 * i;
            cpa4(s2u(&As[bb][lk][row]), &A[(size_t)(n0 + row) * MDIM + k0 + lk]);
            const int mc = (row < FEAT) ? row : 0;
            cpa4p(s2u(&Bs[bb][lk][row]), &W[(size_t)mc * MDIM + k0 + lk], (row < FEAT) ? 4 : 0);
        }
        cp_commit();
    };
    issue(0, 0);
    for (int c = 0; c < 32; c++) {
        if (c + 1 < 32) { issue((c + 1) * 16, (c + 1) & 1); cp_wait1(); }
        else            { cp_wait0(); }
        __syncthreads();
        const int p = c & 1;
#pragma unroll
        for (int kk = 0; kk < 16; kk++) {
            float4 a4 = *(const float4*)&As[p][kk][ty * 4];
            float4 b4 = *(const float4*)&Bs[p][kk][tx * 4];
            float av[4] = {a4.x, a4.y, a4.z, a4.w};
            float bv[4] = {b4.x, b4.y, b4.z, b4.w};
#pragma unroll
            for (int r = 0; r < 4; r++)
#pragma unroll
                for (int c2 = 0; c2 < 4; c2++)
                    acc[r][c2] += av[r] * bv[c2];
        }
        __syncthreads();
    }
#pragma unroll
    for (int r = 0; r < 4; r++) {
        const int n = n0 + ty * 4 + r;
#pragma unroll
        for (int c2 = 0; c2 < 4; c2++) {
            const int m = tx * 4 + c2;
            if (m < FEAT) {
                float v = acc[r][c2] + b[m];
                pred[(size_t)n * 1250 + m] = v;
                __nv_bfloat16 h = __float2bfloat16(v);
                yhi[(size_t)n * 64 + m] = h;
                ylo[(size_t)n * 64 + m] = __float2bfloat16(v - __bfloat162float(h));
            }
        }
    }
}

// ---------------- mma.sync GEMM (bf16 3-term split), TM=64 x TN=128 ----------
// 256 threads = 8 warps (2 M x 4 N), warp tile 32x32.
// Per-ks: ALL fragment loads (A + both pr B groups) issue before the 24-MMA burst,
// so the tensor pipe gets an unbroken stream. __launch_bounds__(256,2) keeps 2 CTAs/SM.
// EPI: 0 = LSTM cell (TN = 4 gates x 32 j, j0 = bn*32), 1 = tanh->bf16, 2 = tanh->fp32
template <int NCH, int HASX, int EPI>
__global__ void __launch_bounds__(256, 2)
mma_kernel(const __nv_bfloat16* __restrict__ ahi, const __nv_bfloat16* __restrict__ alo,
           const __nv_bfloat16* __restrict__ xhi, const __nv_bfloat16* __restrict__ xlo,
           const __nv_bfloat16* __restrict__ Bth, const __nv_bfloat16* __restrict__ Btl,
           const float* __restrict__ base, int base_stride,
           const float* __restrict__ bias,
           float* __restrict__ c_io, float* __restrict__ hF,
           __nv_bfloat16* __restrict__ ohi, __nv_bfloat16* __restrict__ olo,
           float* __restrict__ outF) {
    extern __shared__ __align__(1024) char smem[];
    const int tid = threadIdx.x;
    const int wid = tid >> 5;
    const int lane = tid & 31;
    const int n0 = blockIdx.x * 64;
    const int bn = blockIdx.y;
    const int wm = wid & 1;        // M block (32 rows)
    const int wn = wid >> 1;       // N block (32 cols)
    const int ldAmain = (NCH - HASX) * 128;   // bytes per A row

    float acc[2][4][4] = {};       // [mi][pr*2+t2][frag]

    auto do_copy = [&](int c, int p) {
        char* bb = smem + p * BUF_BYTES;
        uint32_t sAh = s2u(bb), sAl = sAh + TILE_A_BYTES;
        uint32_t sBh = sAh + 2 * TILE_A_BYTES, sBl = sBh + TILE_B_BYTES;
        const char *ap, *alp; int ld;
        if (HASX && c == NCH - 1) { ap = (const char*)xhi; alp = (const char*)xlo; ld = 128; }
        else { ap = (const char*)ahi + c * 128; alp = (const char*)alo + c * 128; ld = ldAmain; }
#pragma unroll
        for (int i = 0; i < 2; i++) {
            int u = tid + i * 256;         // 512 units of 16B for 64x128B tile
            int r = u >> 3, c16 = u & 7;
            uint32_t so = SWZ((uint32_t)(r * 128 + c16 * 16));
            cpa16(sAh + so, ap + (size_t)(n0 + r) * ld + c16 * 16);
            cpa16(sAl + so, alp + (size_t)(n0 + r) * ld + c16 * 16);
        }
        const char* bh = (const char*)Bth + (size_t)(bn * NCH + c) * TILE_B_BYTES;
        const char* bl = (const char*)Btl + (size_t)(bn * NCH + c) * TILE_B_BYTES;
#pragma unroll
        for (int i = 0; i < 4; i++) {
            int u = tid + i * 256;         // 1024 units for 128x128B tile
            cpa16(sBh + u * 16, bh + (size_t)u * 16);
            cpa16(sBl + u * 16, bl + (size_t)u * 16);
        }
        cp_commit();
    };

    do_copy(0, 0);
    if (NCH > 1) do_copy(1, 1);
    for (int c = 0; c < NCH; c++) {
        const int p = c & 1;
        if (c + 1 < NCH) cp_wait1(); else cp_wait0();
        __syncthreads();
        uint32_t baseu = s2u(smem + p * BUF_BYTES);
        uint32_t aHb = baseu, aLb = baseu + TILE_A_BYTES;
        uint32_t bHb = baseu + 2 * TILE_A_BYTES, bLb = bHb + TILE_B_BYTES;
#pragma unroll
        for (int ks = 0; ks < 4; ks++) {
            uint32_t ah[2][4], al[2][4];
            uint32_t bh[2][4], bl[2][4];
            // ---- all loads for this ks first ----
#pragma unroll
            for (int mi = 0; mi < 2; mi++) {
                int rowA = wm * 32 + mi * 16 + (lane & 15);
                uint32_t off = SWZ((uint32_t)(rowA * 128 + ks * 32 + (lane >> 4) * 16));
                LDM_X4(ah[mi], aHb + off);
                LDM_X4(al[mi], aLb + off);
            }
#pragma unroll
            for (int pr = 0; pr < 2; pr++) {
                int rowB = wn * 32 + pr * 16 + ((lane >> 4) << 3) + (lane & 7);
                uint32_t offB = SWZ((uint32_t)(rowB * 128 + ks * 32 + ((lane >> 3) & 1) * 16));
                LDM_X4(bh[pr], bHb + offB);
                LDM_X4(bl[pr], bLb + offB);
            }
            // ---- unbroken MMA burst ----
#pragma unroll
            for (int pr = 0; pr < 2; pr++) {
#pragma unroll
                for (int mi = 0; mi < 2; mi++) {
#pragma unroll
                    for (int t2 = 0; t2 < 2; t2++) {
                        float* d = acc[mi][pr * 2 + t2];
                        MMA16816(d, ah[mi], bh[pr] + t2 * 2);
                        MMA16816(d, ah[mi], bl[pr] + t2 * 2);
                        MMA16816(d, al[mi], bh[pr] + t2 * 2);
                    }
                }
            }
        }
        __syncthreads();
        if (c + 2 < NCH) do_copy(c + 2, p);
    }

    // stage accumulators to smem: sAcc[64][128] fp32 (32 KB)
    float* sAcc = (float*)smem;
#pragma unroll
    for (int mi = 0; mi < 2; mi++) {
#pragma unroll
        for (int ni = 0; ni < 4; ni++) {
            int row = wm * 32 + mi * 16 + (lane >> 2);
            int col = wn * 32 + ni * 8 + 2 * (lane & 3);
            *(float2*)&sAcc[row * 128 + col] = make_float2(acc[mi][ni][0], acc[mi][ni][1]);
            *(float2*)&sAcc[(row + 8) * 128 + col] = make_float2(acc[mi][ni][2], acc[mi][ni][3]);
        }
    }
    __syncthreads();

    if (EPI == 0) {
        const int jcol = tid & 31;
        const int rowgrp = tid >> 5;     // 0..7
        const int j = bn * 32 + jcol;
#pragma unroll
        for (int rr = 0; rr < 8; rr++) {
            int row = rr * 8 + rowgrp;
            int n = n0 + row;
            const float* bp = base + (size_t)n * base_stride;
            float iv = sAcc[row * 128 + jcol]      + bp[j];
            float fv = sAcc[row * 128 + 32 + jcol] + bp[512 + j];
            float gv = sAcc[row * 128 + 64 + jcol] + bp[1024 + j];
            float ov = sAcc[row * 128 + 96 + jcol] + bp[1536 + j];
            float cold = c_io[(size_t)n * HID + j];
            float cn = sigf(fv) * cold + sigf(iv) * tanhf(gv);
            float hn = sigf(ov) * tanhf(cn);
            c_io[(size_t)n * HID + j] = cn;
            hF[(size_t)n * HID + j] = hn;
            __nv_bfloat16 h = __float2bfloat16(hn);
            ohi[(size_t)n * HID + j] = h;
            olo[(size_t)n * HID + j] = __float2bfloat16(hn - __bfloat162float(h));
        }
    } else {
        const int col = tid & 127;
        const int rowgrp = tid >> 7;     // 0..1
        const int gcol = bn * 128 + col;
#pragma unroll
        for (int rr = 0; rr < 32; rr++) {
            int row = rr * 2 + rowgrp;
            int n = n0 + row;
            float v = tanhf(sAcc[row * 128 + col] + bias[gcol]);
            if (EPI == 2) {
                outF[(size_t)n * MDIM + gcol] = v;
            } else {
                __nv_bfloat16 h = __float2bfloat16(v);
                ohi[(size_t)n * MDIM + gcol] = h;
                olo[(size_t)n * MDIM + gcol] = __float2bfloat16(v - __bfloat162float(h));
            }
        }
    }
}

// ---------------- fused 3DMM head ----------------
__global__ void __launch_bounds__(256)
head3dmm_kernel(const float* __restrict__ pred,
                const float* __restrict__ C1, const float* __restrict__ b1,
                const float* __restrict__ C2, const float* __restrict__ b2,
                float* __restrict__ coeff) {
    __shared__ __align__(16) float sP[64][FEAT + 1];
    __shared__ __align__(16) float sC1c[64][FEAT + 1];
    __shared__ __align__(16) float sHid[64][64];
    const int tid = threadIdx.x;
    const int r0 = blockIdx.x * 64;
    for (int i = tid; i < 64 * FEAT; i += 256)
        sP[i / FEAT][i % FEAT] = pred[(size_t)(r0 + i / FEAT) * FEAT + i % FEAT];
    const int row = tid >> 2;
    const int l4 = tid & 3;
    float acc[15];
#pragma unroll
    for (int q = 0; q < 15; q++) acc[q] = 0.0f;
    for (int jc = 0; jc < HID; jc += 64) {
        __syncthreads();
        for (int i = tid; i < 64 * FEAT; i += 256)
            sC1c[i / FEAT][i % FEAT] = C1[(size_t)(jc + i / FEAT) * FEAT + i % FEAT];
        __syncthreads();
#pragma unroll
        for (int jj = 0; jj < 16; jj++) {
            const int jl = l4 * 16 + jj;
            float v = b1[jc + jl];
#pragma unroll
            for (int k = 0; k < FEAT; k++)
                v += sP[row][k] * sC1c[jl][k];
            sHid[row][jl] = tanhf(v);
        }
        __syncthreads();
        for (int q = 0; q < 15; q++) {
            const int m = l4 + q * 4;
            if (m < NC3D) {
                float s = 0.0f;
                const float* c2r = C2 + (size_t)m * HID + jc;
#pragma unroll
                for (int jj = 0; jj < 64; jj++)
                    s += sHid[row][jj] * c2r[jj];
                acc[q] += s;
            }
        }
    }
#pragma unroll
    for (int q = 0; q < 15; q++) {
        const int m = l4 + q * 4;
        if (m < NC3D)
            coeff[(size_t)(r0 + row) * NC3D + m] = acc[q] + b2[m];
    }
}

// ---------------- host orchestration ----------------
extern "C" void kernel_launch(void* const* d_in, const int* in_sizes, int n_in,
                              void* d_out, int out_size) {
    const float* em   = (const float*)d_in[0];
    const float* eWih = (const float*)d_in[2];
    const float* eWhh = (const float*)d_in[3];
    const float* ebih = (const float*)d_in[4];
    const float* ebhh = (const float*)d_in[5];
    const float* muW  = (const float*)d_in[6];
    const float* mub  = (const float*)d_in[7];
    const float* lvW  = (const float*)d_in[8];
    const float* lvb  = (const float*)d_in[9];
    const float* zW   = (const float*)d_in[10];
    const float* zb   = (const float*)d_in[11];
    const float* dWih = (const float*)d_in[12];
    const float* dWhh = (const float*)d_in[13];
    const float* dbih = (const float*)d_in[14];
    const float* dbhh = (const float*)d_in[15];
    const float* m1W  = (const float*)d_in[16];
    const float* m1b  = (const float*)d_in[17];
    const float* m2W  = (const float*)d_in[18];
    const float* m2b  = (const float*)d_in[19];
    const float* oW   = (const float*)d_in[20];
    const float* ob   = (const float*)d_in[21];
    const float* c1W  = (const float*)d_in[22];
    const float* c1b  = (const float*)d_in[23];
    const float* c2W  = (const float*)d_in[24];
    const float* c2b  = (const float*)d_in[25];

    float* out   = (float*)d_out;
    float* pred  = out;
    float* coeff = out + 2400000;
    float* mu    = out + 2400000 + 5568000;
    float* lv    = mu + 491520;

    float *cbuf, *hF, *hy, *base, *m2, *encb;
    __nv_bfloat16 *hbf, *m1bf, *xbf, *ybf, *Benc, *Bdec, *Bm1, *Bm2;
    cudaGetSymbolAddress((void**)&cbuf, g_c);
    cudaGetSymbolAddress((void**)&hF,   g_hF);
    cudaGetSymbolAddress((void**)&hy,   g_hy);
    cudaGetSymbolAddress((void**)&base, g_base);
    cudaGetSymbolAddress((void**)&m2,   g_m2);
    cudaGetSymbolAddress((void**)&encb, g_encb);
    cudaGetSymbolAddress((void**)&hbf,  g_hbf);
    cudaGetSymbolAddress((void**)&m1bf, g_m1bf);
    cudaGetSymbolAddress((void**)&xbf,  g_xbf);
    cudaGetSymbolAddress((void**)&ybf,  g_ybf);
    cudaGetSymbolAddress((void**)&Benc, g_Benc);
    cudaGetSymbolAddress((void**)&Bdec, g_Bdec);
    cudaGetSymbolAddress((void**)&Bm1,  g_Bm1);
    cudaGetSymbolAddress((void**)&Bm2,  g_Bm2);
    const size_t HSZ = (size_t)BEFF * HID;
    const size_t XSL = (size_t)BEFF * 64;
    __nv_bfloat16* hbfp[2][2] = {{hbf, hbf + HSZ}, {hbf + 2 * HSZ, hbf + 3 * HSZ}};
    __nv_bfloat16* BencL = Benc + 16 * 9 * TILE_B_ELEMS;
    __nv_bfloat16* BdecL = Bdec + 16 * 9 * TILE_B_ELEMS;
    __nv_bfloat16* Bm1L = Bm1 + 4 * 8 * TILE_B_ELEMS;
    __nv_bfloat16* Bm2L = Bm2 + 4 * 8 * TILE_B_ELEMS;
    __nv_bfloat16* xlo = xbf + (size_t)WSTEPS * XSL;
    __nv_bfloat16* ylo = ybf + (size_t)(WSTEPS + 1) * XSL;

    cudaFuncSetAttribute(mma_kernel<9,1,0>, cudaFuncAttributeMaxDynamicSharedMemorySize, DYN_SMEM);
    cudaFuncSetAttribute(mma_kernel<8,0,1>, cudaFuncAttributeMaxDynamicSharedMemorySize, DYN_SMEM);
    cudaFuncSetAttribute(mma_kernel<8,0,2>, cudaFuncAttributeMaxDynamicSharedMemorySize, DYN_SMEM);

    const dim3 blk(256);
    // launch 1: all weight conversions
    convAll_kernel<<<1408, blk>>>(eWhh, eWih, dWhh, dWih + 512, m1W, m2W,
                                  Benc, BencL, Bdec, BdecL, Bm1, Bm1L, Bm2, Bm2L);
    // launch 2: zeros + x conversion + enc bias
    prep_kernel<<<2048, blk>>>(em, xbf, xlo, ebih, ebhh, encb,
                               (uint4*)cbuf, (uint4*)hbfp[0][0], (uint4*)hbfp[0][1]);

    // ---- encoder ----
    for (int t = 0; t < WSTEPS; t++) {
        int s = t & 1, d = s ^ 1;
        mma_kernel<9,1,0><<<dim3(30, 16), blk, DYN_SMEM>>>(
            hbfp[s][0], hbfp[s][1], xbf + (size_t)t * XSL, xlo + (size_t)t * XSL,
            Benc, BencL, encb, 0, nullptr, cbuf, hF, hbfp[d][0], hbfp[d][1], nullptr);
    }

    // ---- latent head ----
    gemm_kernel<0><<<dim3(30, 4), blk>>>(hF, HID, muW, HID, mub, nullptr, mu, ZDIM, ZDIM, HID);
    gemm_kernel<0><<<dim3(30, 4), blk>>>(hF, HID, lvW, HID, lvb, nullptr, lv, ZDIM, ZDIM, HID);
    gemm_kernel<0><<<dim3(30, 8), blk>>>(mu, ZDIM, zW, ZDIM, zb, nullptr, hy, HID, HID, ZDIM);
    gemm_kernel<0><<<dim3(30, 32), blk>>>(hy, HID, dWih, HID + FEAT, dbih, dbhh,
                                          base, GATES, GATES, HID);

    // reset state for decoder (1 launch)
    zero3_kernel<<<512, blk>>>((uint4*)cbuf, (uint4*)hbfp[0][0], (uint4*)hbfp[0][1]);

    // ---- decoder ----
    for (int t = 0; t < WSTEPS; t++) {
        int s = t & 1, d = s ^ 1;
        const __nv_bfloat16* yh = (t == 0) ? (ybf + (size_t)WSTEPS * XSL) : (ybf + (size_t)(t - 1) * XSL);
        const __nv_bfloat16* yl = (t == 0) ? (ylo + (size_t)WSTEPS * XSL) : (ylo + (size_t)(t - 1) * XSL);
        mma_kernel<9,1,0><<<dim3(30, 16), blk, DYN_SMEM>>>(
            hbfp[s][0], hbfp[s][1], yh, yl,
            Bdec, BdecL, base, GATES, nullptr, cbuf, hF, hbfp[d][0], hbfp[d][1], nullptr);
        mma_kernel<8,0,1><<<dim3(30, 4), blk, DYN_SMEM>>>(
            hbfp[d][0], hbfp[d][1], nullptr, nullptr,
            Bm1, Bm1L, nullptr, 0, m1b, nullptr, nullptr, m1bf, m1bf + HSZ, nullptr);
        mma_kernel<8,0,2><<<dim3(30, 4), blk, DYN_SMEM>>>(
            m1bf, m1bf + HSZ, nullptr, nullptr,
            Bm2, Bm2L, nullptr, 0, m2b, nullptr, nullptr, nullptr, nullptr, m2);
        outproj_kernel<<<30, blk>>>(m2, oW, ob, pred + t * FEAT,
                                    ybf + (size_t)t * XSL, ylo + (size_t)t * XSL);
    }

    // ---- 3DMM head ----
    head3dmm_kernel<<<1500, blk>>>(pred, c1W, c1b, c2W, c2b, coeff);
}

// round 16
// speedup vs baseline: 2.0250x; 1.0411x over previous
#include <cuda_runtime.h>
#include <cuda_bf16.h>
#include <math.h>
#include <stdint.h>

#define BEFF   1920
#define HID    512
#define FEAT   25
#define ZDIM   256
#define MDIM   512
#define NC3D   58
#define WSTEPS 50
#define GATES  2048

// tile config: TM=64 rows x TN=128 cols, chunks of K=64
#define TILE_A_BYTES 8192               // 64 rows x 128 B
#define TILE_B_BYTES 16384              // 128 rows x 128 B
#define TILE_B_ELEMS 8192
#define BUF_BYTES (2*TILE_A_BYTES + 2*TILE_B_BYTES)   // 49152
#define DYN_SMEM (2*BUF_BYTES)                         // 98304 (2 CTAs/SM)

// ---------------- device scratch ----------------
__device__ float g_c[BEFF * HID];
__device__ float g_hF[BEFF * HID];
__device__ float g_hy[BEFF * HID];
__device__ float g_base[BEFF * GATES];
__device__ float g_m2[BEFF * MDIM];
__device__ float g_encb[GATES];
__device__ __align__(256) __nv_bfloat16 g_hbf[2][2][BEFF * HID];
__device__ __align__(256) __nv_bfloat16 g_m1bf[2][BEFF * MDIM];
__device__ __align__(256) __nv_bfloat16 g_xbf[2][WSTEPS * BEFF * 64];
__device__ __align__(256) __nv_bfloat16 g_ybf[2][(WSTEPS + 1) * BEFF * 64]; // slot WSTEPS stays 0
__device__ __align__(256) __nv_bfloat16 g_Benc[2][16 * 9 * TILE_B_ELEMS];
__device__ __align__(256) __nv_bfloat16 g_Bdec[2][16 * 9 * TILE_B_ELEMS];
__device__ __align__(256) __nv_bfloat16 g_Bm1[2][4 * 8 * TILE_B_ELEMS];
__device__ __align__(256) __nv_bfloat16 g_Bm2[2][4 * 8 * TILE_B_ELEMS];

// ---------------- helpers ----------------
__device__ __forceinline__ float sigf(float x) { return 1.0f / (1.0f + __expf(-x)); }
__device__ __forceinline__ uint32_t s2u(const void* p) {
    return (uint32_t)__cvta_generic_to_shared(p);
}
__device__ __forceinline__ void cpa4(uint32_t d, const void* s) {
    asm volatile("cp.async.ca.shared.global [%0], [%1], 4;" :: "r"(d), "l"(s));
}
__device__ __forceinline__ void cpa4p(uint32_t d, const void* s, int sz) {
    asm volatile("cp.async.ca.shared.global [%0], [%1], 4, %2;" :: "r"(d), "l"(s), "r"(sz));
}
__device__ __forceinline__ void cpa16(uint32_t d, const void* s) {
    asm volatile("cp.async.cg.shared.global [%0], [%1], 16;" :: "r"(d), "l"(s));
}
__device__ __forceinline__ void cp_commit() { asm volatile("cp.async.commit_group;"); }
__device__ __forceinline__ void cp_wait0()  { asm volatile("cp.async.wait_group 0;"); }
__device__ __forceinline__ void cp_wait1()  { asm volatile("cp.async.wait_group 1;"); }

#define SWZ(o) ((o) ^ (((o) >> 3) & 0x70))

#define LDM_X4(r, a) \
    asm volatile("ldmatrix.sync.aligned.m8n8.x4.shared.b16 {%0,%1,%2,%3}, [%4];" \
        : "=r"((r)[0]), "=r"((r)[1]), "=r"((r)[2]), "=r"((r)[3]) : "r"(a))

#define MMA16816(d, a, b) \
    asm volatile("mma.sync.aligned.m16n8k16.row.col.f32.bf16.bf16.f32 " \
        "{%0,%1,%2,%3}, {%4,%5,%6,%7}, {%8,%9}, {%0,%1,%2,%3};" \
        : "+f"((d)[0]), "+f"((d)[1]), "+f"((d)[2]), "+f"((d)[3]) \
        : "r"((a)[0]), "r"((a)[1]), "r"((a)[2]), "r"((a)[3]), "r"((b)[0]), "r"((b)[1]))

// ---------------- fused init kernels --------------------------------------
// Build pre-swizzled bf16 hi/lo B tiles: blocks of 128 rows x 64 k (16 KB).
// gateBlocked: tile row r -> weight row (r>>5)*HID + bn*32 + (r&31)
__device__ __forceinline__ void conv_unit(int u, const float* W, int ldw, int Kmain,
                                          int gateBlocked, const float* Wx, int ldx, int Kx,
                                          int nCh,
                                          __nv_bfloat16* outHi, __nv_bfloat16* outLo) {
    int bn = u / (nCh * 1024);
    int rem = u - bn * nCh * 1024;
    int c = rem / 1024;
    int unit = rem & 1023;
    int r = unit >> 3, c16 = unit & 7;
    int srow = gateBlocked ? ((r >> 5) * HID + bn * 32 + (r & 31)) : (bn * 128 + r);
    bool xc = (Wx != nullptr) && (c == nCh - 1);
    unsigned short hb[8], lb[8];
#pragma unroll
    for (int e = 0; e < 8; e++) {
        int k = c16 * 8 + e;
        float v;
        if (xc) v = (k < Kx) ? Wx[(size_t)srow * ldx + k] : 0.0f;
        else {
            int kk = c * 64 + k;
            v = (kk < Kmain) ? W[(size_t)srow * ldw + kk] : 0.0f;
        }
        __nv_bfloat16 h = __float2bfloat16(v);
        hb[e] = __bfloat16_as_ushort(h);
        lb[e] = __bfloat16_as_ushort(__float2bfloat16(v - __bfloat162float(h)));
    }
    uint32_t so = SWZ((uint32_t)(r * 128 + c16 * 16));
    size_t dstu = (size_t)(bn * nCh + c) * 1024 + (so >> 4);
    uint4 vh, vl;
    vh.x = hb[0] | (hb[1] << 16); vh.y = hb[2] | (hb[3] << 16);
    vh.z = hb[4] | (hb[5] << 16); vh.w = hb[6] | (hb[7] << 16);
    vl.x = lb[0] | (lb[1] << 16); vl.y = lb[2] | (lb[3] << 16);
    vl.z = lb[4] | (lb[5] << 16); vl.w = lb[6] | (lb[7] << 16);
    ((uint4*)outHi)[dstu] = vh;
    ((uint4*)outLo)[dstu] = vl;
}

__global__ void convAll_kernel(const float* eWhh, const float* eWih,
                               const float* dWhh, const float* dWih512,
                               const float* m1W, const float* m2W,
                               __nv_bfloat16* Benc, __nv_bfloat16* BencL,
                               __nv_bfloat16* Bdec, __nv_bfloat16* BdecL,
                               __nv_bfloat16* Bm1, __nv_bfloat16* Bm1L,
                               __nv_bfloat16* Bm2, __nv_bfloat16* Bm2L) {
    const int ENC_U = 16 * 9 * 1024;  // 147456
    const int MLP_U = 4 * 8 * 1024;   // 32768
    const int total = 2 * ENC_U + 2 * MLP_U;
    for (int u = blockIdx.x * blockDim.x + threadIdx.x; u < total;
         u += gridDim.x * blockDim.x) {
        if (u < ENC_U)
            conv_unit(u, eWhh, 512, 512, 1, eWih, 25, 25, 9, Benc, BencL);
        else if (u < 2 * ENC_U)
            conv_unit(u - ENC_U, dWhh, 512, 512, 1, dWih512, 537, 25, 9, Bdec, BdecL);
        else if (u < 2 * ENC_U + MLP_U)
            conv_unit(u - 2 * ENC_U, m1W, 512, 512, 0, nullptr, 0, 0, 8, Bm1, Bm1L);
        else
            conv_unit(u - 2 * ENC_U - MLP_U, m2W, 512, 512, 0, nullptr, 0, 0, 8, Bm2, Bm2L);
    }
}

// zeros (c, h-hi, h-lo) + x conversion + enc bias add, one launch
__global__ void prep_kernel(const float* __restrict__ em,
                            __nv_bfloat16* __restrict__ xhi, __nv_bfloat16* __restrict__ xlo,
                            const float* __restrict__ b1, const float* __restrict__ b2,
                            float* __restrict__ encb,
                            uint4* __restrict__ zc, uint4* __restrict__ zh0,
                            uint4* __restrict__ zh1) {
    const int NZC = BEFF * HID / 4;
    const int NZH = BEFF * HID / 8;
    const int NCX = WSTEPS * BEFF * 64;
    const int total = NZC + 2 * NZH + NCX + GATES;
    uint4 z = {0, 0, 0, 0};
    for (int u = blockIdx.x * blockDim.x + threadIdx.x; u < total;
         u += gridDim.x * blockDim.x) {
        if (u < NZC) { zc[u] = z; }
        else if (u < NZC + NZH) { zh0[u - NZC] = z; }
        else if (u < NZC + 2 * NZH) { zh1[u - NZC - NZH] = z; }
        else if (u < NZC + 2 * NZH + NCX) {
            int idx = u - (NZC + 2 * NZH);
            int t = idx / (BEFF * 64);
            int rem = idx - t * BEFF * 64;
            int i = rem >> 6, k = rem & 63;
            float v = (k < FEAT) ? em[(size_t)i * 1250 + t * FEAT + k] : 0.0f;
            __nv_bfloat16 h = __float2bfloat16(v);
            xhi[idx] = h;
            xlo[idx] = __float2bfloat16(v - __bfloat162float(h));
        } else {
            int i = u - (NZC + 2 * NZH + NCX);
            encb[i] = b1[i] + b2[i];
        }
    }
}

__global__ void zero3_kernel(uint4* __restrict__ zc, uint4* __restrict__ zh0,
                             uint4* __restrict__ zh1) {
    const int NZC = BEFF * HID / 4;
    const int NZH = BEFF * HID / 8;
    const int total = NZC + 2 * NZH;
    uint4 z = {0, 0, 0, 0};
    for (int u = blockIdx.x * blockDim.x + threadIdx.x; u < total;
         u += gridDim.x * blockDim.x) {
        if (u < NZC) zc[u] = z;
        else if (u < NZC + NZH) zh0[u - NZC] = z;
        else zh1[u - NZC - NZH] = z;
    }
}

// ---------------- SIMT GEMM (small shapes) ----------------
template <int ACT>
__global__ void __launch_bounds__(256, 2)
gemm_kernel(const float* __restrict__ A, int lda,
            const float* __restrict__ W, int ldw,
            const float* __restrict__ b1, const float* __restrict__ b2,
            float* __restrict__ C, int ldc, int N, int K) {
    __shared__ __align__(16) float As[2][16][68];
    __shared__ __align__(16) float Bs[2][16][68];
    const int tid = threadIdx.x;
    const int tx = tid & 15, ty = tid >> 4;
    const int n0 = blockIdx.x * 64, m0 = blockIdx.y * 64;
    const int lk = tid & 15, lr = tid >> 4;
    float acc[4][4] = {};
    const int nch = K >> 4;
    auto issue = [&](int k0, int b) {
#pragma unroll
        for (int i = 0; i < 4; i++) {
            const int row = lr + 16 * i;
            cpa4(s2u(&As[b][lk][row]), &A[(size_t)(n0 + row) * lda + k0 + lk]);
            const int m = m0 + row;
            const int mc = (m < N) ? m : 0;
            cpa4p(s2u(&Bs[b][lk][row]), &W[(size_t)mc * ldw + k0 + lk], (m < N) ? 4 : 0);
        }
        cp_commit();
    };
    issue(0, 0);
    for (int c = 0; c < nch; c++) {
        if (c + 1 < nch) { issue((c + 1) * 16, (c + 1) & 1); cp_wait1(); }
        else             { cp_wait0(); }
        __syncthreads();
        const int p = c & 1;
#pragma unroll
        for (int kk = 0; kk < 16; kk++) {
            float4 a4 = *(const float4*)&As[p][kk][ty * 4];
            float4 b4 = *(const float4*)&Bs[p][kk][tx * 4];
            float av[4] = {a4.x, a4.y, a4.z, a4.w};
            float bv[4] = {b4.x, b4.y, b4.z, b4.w};
#pragma unroll
            for (int r = 0; r < 4; r++)
#pragma unroll
                for (int c2 = 0; c2 < 4; c2++)
                    acc[r][c2] += av[r] * bv[c2];
        }
        __syncthreads();
    }
#pragma unroll
    for (int r = 0; r < 4; r++) {
        const int n = n0 + ty * 4 + r;
#pragma unroll
        for (int c2 = 0; c2 < 4; c2++) {
            const int m = m0 + tx * 4 + c2;
            if (m < N) {
                float v = acc[r][c2];
                if (b1) v += b1[m];
                if (b2) v += b2[m];
                if (ACT == 1) v = tanhf(v);
                C[(size_t)n * ldc + m] = v;
            }
        }
    }
}

// out projection: warp-per-row, shuffle reduce. grid 240 x 256 thr (8 rows/CTA).
__global__ void __launch_bounds__(256)
outproj_kernel(const float* __restrict__ A, const float* __restrict__ W,
               const float* __restrict__ b, float* __restrict__ pred,
               __nv_bfloat16* __restrict__ yhi, __nv_bfloat16* __restrict__ ylo) {
    const int w = threadIdx.x >> 5, lane = threadIdx.x & 31;
    const int n = blockIdx.x * 8 + w;
    float a[16];
#pragma unroll
    for (int q = 0; q < 16; q++)
        a[q] = A[(size_t)n * MDIM + q * 32 + lane];
#pragma unroll 5
    for (int col = 0; col < FEAT; col++) {
        const float* wr = W + (size_t)col * MDIM;
        float s = 0.0f;
#pragma unroll
        for (int q = 0; q < 16; q++)
            s += a[q] * wr[q * 32 + lane];
#pragma unroll
        for (int o = 16; o; o >>= 1)
            s += __shfl_xor_sync(0xffffffffu, s, o);
        if (lane == 0) {
            float v = s + b[col];
            pred[(size_t)n * 1250 + col] = v;
            __nv_bfloat16 h = __float2bfloat16(v);
            yhi[(size_t)n * 64 + col] = h;
            ylo[(size_t)n * 64 + col] = __float2bfloat16(v - __bfloat162float(h));
        }
    }
}

// ---------------- mma.sync GEMM (bf16 3-term split), TM=64 x TN=128 ----------
// 256 threads = 8 warps (2 M x 4 N), warp tile 32x32, 2 CTAs/SM.
// MMA burst is TERM-MAJOR: each acc register is touched once per 8 MMAs,
// breaking the 3-deep dependent-MMA chain that capped issue at ~25%.
// EPI: 0 = LSTM cell (TN = 4 gates x 32 j, j0 = bn*32), 1 = tanh->bf16, 2 = tanh->fp32
template <int NCH, int HASX, int EPI>
__global__ void __launch_bounds__(256, 2)
mma_kernel(const __nv_bfloat16* __restrict__ ahi, const __nv_bfloat16* __restrict__ alo,
           const __nv_bfloat16* __restrict__ xhi, const __nv_bfloat16* __restrict__ xlo,
           const __nv_bfloat16* __restrict__ Bth, const __nv_bfloat16* __restrict__ Btl,
           const float* __restrict__ base, int base_stride,
           const float* __restrict__ bias,
           float* __restrict__ c_io, float* __restrict__ hF,
           __nv_bfloat16* __restrict__ ohi, __nv_bfloat16* __restrict__ olo,
           float* __restrict__ outF) {
    extern __shared__ __align__(1024) char smem[];
    const int tid = threadIdx.x;
    const int wid = tid >> 5;
    const int lane = tid & 31;
    const int n0 = blockIdx.x * 64;
    const int bn = blockIdx.y;
    const int wm = wid & 1;        // M block (32 rows)
    const int wn = wid >> 1;       // N block (32 cols)
    const int ldAmain = (NCH - HASX) * 128;   // bytes per A row

    float acc[2][4][4] = {};       // [mi][pr*2+t2][frag]

    auto do_copy = [&](int c, int p) {
        char* bb = smem + p * BUF_BYTES;
        uint32_t sAh = s2u(bb), sAl = sAh + TILE_A_BYTES;
        uint32_t sBh = sAh + 2 * TILE_A_BYTES, sBl = sBh + TILE_B_BYTES;
        const char *ap, *alp; int ld;
        if (HASX && c == NCH - 1) { ap = (const char*)xhi; alp = (const char*)xlo; ld = 128; }
        else { ap = (const char*)ahi + c * 128; alp = (const char*)alo + c * 128; ld = ldAmain; }
#pragma unroll
        for (int i = 0; i < 2; i++) {
            int u = tid + i * 256;         // 512 units of 16B for 64x128B tile
            int r = u >> 3, c16 = u & 7;
            uint32_t so = SWZ((uint32_t)(r * 128 + c16 * 16));
            cpa16(sAh + so, ap + (size_t)(n0 + r) * ld + c16 * 16);
            cpa16(sAl + so, alp + (size_t)(n0 + r) * ld + c16 * 16);
        }
        const char* bh = (const char*)Bth + (size_t)(bn * NCH + c) * TILE_B_BYTES;
        const char* bl = (const char*)Btl + (size_t)(bn * NCH + c) * TILE_B_BYTES;
#pragma unroll
        for (int i = 0; i < 4; i++) {
            int u = tid + i * 256;         // 1024 units for 128x128B tile
            cpa16(sBh + u * 16, bh + (size_t)u * 16);
            cpa16(sBl + u * 16, bl + (size_t)u * 16);
        }
        cp_commit();
    };

    do_copy(0, 0);
    if (NCH > 1) do_copy(1, 1);
    for (int c = 0; c < NCH; c++) {
        const int p = c & 1;
        if (c + 1 < NCH) cp_wait1(); else cp_wait0();
        __syncthreads();
        uint32_t baseu = s2u(smem + p * BUF_BYTES);
        uint32_t aHb = baseu, aLb = baseu + TILE_A_BYTES;
        uint32_t bHb = baseu + 2 * TILE_A_BYTES, bLb = bHb + TILE_B_BYTES;
#pragma unroll
        for (int ks = 0; ks < 4; ks++) {
            uint32_t ah[2][4], al[2][4];
            uint32_t bh[2][4], bl[2][4];
            // ---- all loads for this ks first ----
#pragma unroll
            for (int mi = 0; mi < 2; mi++) {
                int rowA = wm * 32 + mi * 16 + (lane & 15);
                uint32_t off = SWZ((uint32_t)(rowA * 128 + ks * 32 + (lane >> 4) * 16));
                LDM_X4(ah[mi], aHb + off);
                LDM_X4(al[mi], aLb + off);
            }
#pragma unroll
            for (int pr = 0; pr < 2; pr++) {
                int rowB = wn * 32 + pr * 16 + ((lane >> 4) << 3) + (lane & 7);
                uint32_t offB = SWZ((uint32_t)(rowB * 128 + ks * 32 + ((lane >> 3) & 1) * 16));
                LDM_X4(bh[pr], bHb + offB);
                LDM_X4(bl[pr], bLb + offB);
            }
            // ---- term-major MMA burst: each acc touched once per 8 MMAs ----
#pragma unroll
            for (int term = 0; term < 3; term++) {
#pragma unroll
                for (int pr = 0; pr < 2; pr++) {
#pragma unroll
                    for (int mi = 0; mi < 2; mi++) {
#pragma unroll
                        for (int t2 = 0; t2 < 2; t2++) {
                            float* d = acc[mi][pr * 2 + t2];
                            const uint32_t* aa = (term == 2) ? al[mi] : ah[mi];
                            const uint32_t* bb = (term == 1) ? bl[pr] : bh[pr];
                            MMA16816(d, aa, bb + t2 * 2);
                        }
                    }
                }
            }
        }
        __syncthreads();
        if (c + 2 < NCH) do_copy(c + 2, p);
    }

    // stage accumulators to smem: sAcc[64][128] fp32 (32 KB)
    float* sAcc = (float*)smem;
#pragma unroll
    for (int mi = 0; mi < 2; mi++) {
#pragma unroll
        for (int ni = 0; ni < 4; ni++) {
            int row = wm * 32 + mi * 16 + (lane >> 2);
            int col = wn * 32 + ni * 8 + 2 * (lane & 3);
            *(float2*)&sAcc[row * 128 + col] = make_float2(acc[mi][ni][0], acc[mi][ni][1]);
            *(float2*)&sAcc[(row + 8) * 128 + col] = make_float2(acc[mi][ni][2], acc[mi][ni][3]);
        }
    }
    __syncthreads();

    if (EPI == 0) {
        const int jcol = tid & 31;
        const int rowgrp = tid >> 5;     // 0..7
        const int j = bn * 32 + jcol;
#pragma unroll
        for (int rr = 0; rr < 8; rr++) {
            int row = rr * 8 + rowgrp;
            int n = n0 + row;
            const float* bp = base + (size_t)n * base_stride;
            float iv = sAcc[row * 128 + jcol]      + bp[j];
            float fv = sAcc[row * 128 + 32 + jcol] + bp[512 + j];
            float gv = sAcc[row * 128 + 64 + jcol] + bp[1024 + j];
            float ov = sAcc[row * 128 + 96 + jcol] + bp[1536 + j];
            float cold = c_io[(size_t)n * HID + j];
            float cn = sigf(fv) * cold + sigf(iv) * tanhf(gv);
            float hn = sigf(ov) * tanhf(cn);
            c_io[(size_t)n * HID + j] = cn;
            hF[(size_t)n * HID + j] = hn;
            __nv_bfloat16 h = __float2bfloat16(hn);
            ohi[(size_t)n * HID + j] = h;
            olo[(size_t)n * HID + j] = __float2bfloat16(hn - __bfloat162float(h));
        }
    } else {
        const int col = tid & 127;
        const int rowgrp = tid >> 7;     // 0..1
        const int gcol = bn * 128 + col;
#pragma unroll
        for (int rr = 0; rr < 32; rr++) {
            int row = rr * 2 + rowgrp;
            int n = n0 + row;
            float v = tanhf(sAcc[row * 128 + col] + bias[gcol]);
            if (EPI == 2) {
                outF[(size_t)n * MDIM + gcol] = v;
            } else {
                __nv_bfloat16 h = __float2bfloat16(v);
                ohi[(size_t)n * MDIM + gcol] = h;
                olo[(size_t)n * MDIM + gcol] = __float2bfloat16(v - __bfloat162float(h));
            }
        }
    }
}

// ---------------- fused 3DMM head ----------------
__global__ void __launch_bounds__(256)
head3dmm_kernel(const float* __restrict__ pred,
                const float* __restrict__ C1, const float* __restrict__ b1,
                const float* __restrict__ C2, const float* __restrict__ b2,
                float* __restrict__ coeff) {
    __shared__ __align__(16) float sP[64][FEAT + 1];
    __shared__ __align__(16) float sC1c[64][FEAT + 1];
    __shared__ __align__(16) float sHid[64][64];
    const int tid = threadIdx.x;
    const int r0 = blockIdx.x * 64;
    for (int i = tid; i < 64 * FEAT; i += 256)
        sP[i / FEAT][i % FEAT] = pred[(size_t)(r0 + i / FEAT) * FEAT + i % FEAT];
    const int row = tid >> 2;
    const int l4 = tid & 3;
    float acc[15];
#pragma unroll
    for (int q = 0; q < 15; q++) acc[q] = 0.0f;
    for (int jc = 0; jc < HID; jc += 64) {
        __syncthreads();
        for (int i = tid; i < 64 * FEAT; i += 256)
            sC1c[i / FEAT][i % FEAT] = C1[(size_t)(jc + i / FEAT) * FEAT + i % FEAT];
        __syncthreads();
#pragma unroll
        for (int jj = 0; jj < 16; jj++) {
            const int jl = l4 * 16 + jj;
            float v = b1[jc + jl];
#pragma unroll
            for (int k = 0; k < FEAT; k++)
                v += sP[row][k] * sC1c[jl][k];
            sHid[row][jl] = tanhf(v);
        }
        __syncthreads();
        for (int q = 0; q < 15; q++) {
            const int m = l4 + q * 4;
            if (m < NC3D) {
                float s = 0.0f;
                const float* c2r = C2 + (size_t)m * HID + jc;
#pragma unroll
                for (int jj = 0; jj < 64; jj++)
                    s += sHid[row][jj] * c2r[jj];
                acc[q] += s;
            }
        }
    }
#pragma unroll
    for (int q = 0; q < 15; q++) {
        const int m = l4 + q * 4;
        if (m < NC3D)
            coeff[(size_t)(r0 + row) * NC3D + m] = acc[q] + b2[m];
    }
}

// ---------------- host orchestration ----------------
extern "C" void kernel_launch(void* const* d_in, const int* in_sizes, int n_in,
                              void* d_out, int out_size) {
    const float* em   = (const float*)d_in[0];
    const float* eWih = (const float*)d_in[2];
    const float* eWhh = (const float*)d_in[3];
    const float* ebih = (const float*)d_in[4];
    const float* ebhh = (const float*)d_in[5];
    const float* muW  = (const float*)d_in[6];
    const float* mub  = (const float*)d_in[7];
    const float* lvW  = (const float*)d_in[8];
    const float* lvb  = (const float*)d_in[9];
    const float* zW   = (const float*)d_in[10];
    const float* zb   = (const float*)d_in[11];
    const float* dWih = (const float*)d_in[12];
    const float* dWhh = (const float*)d_in[13];
    const float* dbih = (const float*)d_in[14];
    const float* dbhh = (const float*)d_in[15];
    const float* m1W  = (const float*)d_in[16];
    const float* m1b  = (const float*)d_in[17];
    const float* m2W  = (const float*)d_in[18];
    const float* m2b  = (const float*)d_in[19];
    const float* oW   = (const float*)d_in[20];
    const float* ob   = (const float*)d_in[21];
    const float* c1W  = (const float*)d_in[22];
    const float* c1b  = (const float*)d_in[23];
    const float* c2W  = (const float*)d_in[24];
    const float* c2b  = (const float*)d_in[25];

    float* out   = (float*)d_out;
    float* pred  = out;
    float* coeff = out + 2400000;
    float* mu    = out + 2400000 + 5568000;
    float* lv    = mu + 491520;

    float *cbuf, *hF, *hy, *base, *m2, *encb;
    __nv_bfloat16 *hbf, *m1bf, *xbf, *ybf, *Benc, *Bdec, *Bm1, *Bm2;
    cudaGetSymbolAddress((void**)&cbuf, g_c);
    cudaGetSymbolAddress((void**)&hF,   g_hF);
    cudaGetSymbolAddress((void**)&hy,   g_hy);
    cudaGetSymbolAddress((void**)&base, g_base);
    cudaGetSymbolAddress((void**)&m2,   g_m2);
    cudaGetSymbolAddress((void**)&encb, g_encb);
    cudaGetSymbolAddress((void**)&hbf,  g_hbf);
    cudaGetSymbolAddress((void**)&m1bf, g_m1bf);
    cudaGetSymbolAddress((void**)&xbf,  g_xbf);
    cudaGetSymbolAddress((void**)&ybf,  g_ybf);
    cudaGetSymbolAddress((void**)&Benc, g_Benc);
    cudaGetSymbolAddress((void**)&Bdec, g_Bdec);
    cudaGetSymbolAddress((void**)&Bm1,  g_Bm1);
    cudaGetSymbolAddress((void**)&Bm2,  g_Bm2);
    const size_t HSZ = (size_t)BEFF * HID;
    const size_t XSL = (size_t)BEFF * 64;
    __nv_bfloat16* hbfp[2][2] = {{hbf, hbf + HSZ}, {hbf + 2 * HSZ, hbf + 3 * HSZ}};
    __nv_bfloat16* BencL = Benc + 16 * 9 * TILE_B_ELEMS;
    __nv_bfloat16* BdecL = Bdec + 16 * 9 * TILE_B_ELEMS;
    __nv_bfloat16* Bm1L = Bm1 + 4 * 8 * TILE_B_ELEMS;
    __nv_bfloat16* Bm2L = Bm2 + 4 * 8 * TILE_B_ELEMS;
    __nv_bfloat16* xlo = xbf + (size_t)WSTEPS * XSL;
    __nv_bfloat16* ylo = ybf + (size_t)(WSTEPS + 1) * XSL;

    cudaFuncSetAttribute(mma_kernel<9,1,0>, cudaFuncAttributeMaxDynamicSharedMemorySize, DYN_SMEM);
    cudaFuncSetAttribute(mma_kernel<8,0,1>, cudaFuncAttributeMaxDynamicSharedMemorySize, DYN_SMEM);
    cudaFuncSetAttribute(mma_kernel<8,0,2>, cudaFuncAttributeMaxDynamicSharedMemorySize, DYN_SMEM);

    const dim3 blk(256);
    // launch 1: all weight conversions
    convAll_kernel<<<1408, blk>>>(eWhh, eWih, dWhh, dWih + 512, m1W, m2W,
                                  Benc, BencL, Bdec, BdecL, Bm1, Bm1L, Bm2, Bm2L);
    // launch 2: zeros + x conversion + enc bias
    prep_kernel<<<2048, blk>>>(em, xbf, xlo, ebih, ebhh, encb,
                               (uint4*)cbuf, (uint4*)hbfp[0][0], (uint4*)hbfp[0][1]);

    // ---- encoder ----
    for (int t = 0; t < WSTEPS; t++) {
        int s = t & 1, d = s ^ 1;
        mma_kernel<9,1,0><<<dim3(30, 16), blk, DYN_SMEM>>>(
            hbfp[s][0], hbfp[s][1], xbf + (size_t)t * XSL, xlo + (size_t)t * XSL,
            Benc, BencL, encb, 0, nullptr, cbuf, hF, hbfp[d][0], hbfp[d][1], nullptr);
    }

    // ---- latent head ----
    gemm_kernel<0><<<dim3(30, 4), blk>>>(hF, HID, muW, HID, mub, nullptr, mu, ZDIM, ZDIM, HID);
    gemm_kernel<0><<<dim3(30, 4), blk>>>(hF, HID, lvW, HID, lvb, nullptr, lv, ZDIM, ZDIM, HID);
    gemm_kernel<0><<<dim3(30, 8), blk>>>(mu, ZDIM, zW, ZDIM, zb, nullptr, hy, HID, HID, ZDIM);
    gemm_kernel<0><<<dim3(30, 32), blk>>>(hy, HID, dWih, HID + FEAT, dbih, dbhh,
                                          base, GATES, GATES, HID);

    // reset state for decoder (1 launch)
    zero3_kernel<<<512, blk>>>((uint4*)cbuf, (uint4*)hbfp[0][0], (uint4*)hbfp[0][1]);

    // ---- decoder ----
    for (int t = 0; t < WSTEPS; t++) {
        int s = t & 1, d = s ^ 1;
        const __nv_bfloat16* yh = (t == 0) ? (ybf + (size_t)WSTEPS * XSL) : (ybf + (size_t)(t - 1) * XSL);
        const __nv_bfloat16* yl = (t == 0) ? (ylo + (size_t)WSTEPS * XSL) : (ylo + (size_t)(t - 1) * XSL);
        mma_kernel<9,1,0><<<dim3(30, 16), blk, DYN_SMEM>>>(
            hbfp[s][0], hbfp[s][1], yh, yl,
            Bdec, BdecL, base, GATES, nullptr, cbuf, hF, hbfp[d][0], hbfp[d][1], nullptr);
        mma_kernel<8,0,1><<<dim3(30, 4), blk, DYN_SMEM>>>(
            hbfp[d][0], hbfp[d][1], nullptr, nullptr,
            Bm1, Bm1L, nullptr, 0, m1b, nullptr, nullptr, m1bf, m1bf + HSZ, nullptr);
        mma_kernel<8,0,2><<<dim3(30, 4), blk, DYN_SMEM>>>(
            m1bf, m1bf + HSZ, nullptr, nullptr,
            Bm2, Bm2L, nullptr, 0, m2b, nullptr, nullptr, nullptr, nullptr, m2);
        outproj_kernel<<<240, blk>>>(m2, oW, ob, pred + t * FEAT,
                                     ybf + (size_t)t * XSL, ylo + (size_t)t * XSL);
    }

    // ---- 3DMM head ----
    head3dmm_kernel<<<1500, blk>>>(pred, c1W, c1b, c2W, c2b, coeff);
}